// round 11
// baseline (speedup 1.0000x reference)
#include <cuda_runtime.h>
#include <cuda_bf16.h>
#include <cstdint>

#define NB   2
#define SEQ  2048
#define DM   1024
#define NH   16
#define HD   64
#define MTOT (NB*SEQ)   // 4096

// Scratch (static device globals — allocation-free per harness rules)
__device__ float g_q[MTOT * DM];
__device__ float g_k[MTOT * DM];
__device__ float g_vt[NB * NH * HD * SEQ];    // V^T per (b,h): [HD][SEQ]
__device__ float g_o[MTOT * DM];

// ---------------------------------------------------------------------------
// helpers
// ---------------------------------------------------------------------------
__device__ __forceinline__ uint32_t smem_u32(const void* p) {
    uint32_t a;
    asm("{ .reg .u64 t; cvta.to.shared.u64 t, %1; cvt.u32.u64 %0, t; }"
        : "=r"(a) : "l"(p));
    return a;
}

// 3-term bf16 split: x = hi + lo (hi = bf16(x), lo = bf16(x - hi)).
__device__ __forceinline__ void split2(float x, float y, uint32_t& hi, uint32_t& lo) {
    __nv_bfloat16 hx = __float2bfloat16_rn(x);
    __nv_bfloat16 hy = __float2bfloat16_rn(y);
    float rx = x - __bfloat162float(hx);
    float ry = y - __bfloat162float(hy);
    __nv_bfloat16 lx = __float2bfloat16_rn(rx);
    __nv_bfloat16 ly = __float2bfloat16_rn(ry);
    hi = ((uint32_t)__bfloat16_as_ushort(hy) << 16) | (uint32_t)__bfloat16_as_ushort(hx);
    lo = ((uint32_t)__bfloat16_as_ushort(ly) << 16) | (uint32_t)__bfloat16_as_ushort(lx);
}

__device__ __forceinline__ void ldm4(uint32_t addr, uint32_t r[4]) {
    asm volatile("ldmatrix.sync.aligned.m8n8.x4.shared.b16 {%0,%1,%2,%3}, [%4];"
                 : "=r"(r[0]), "=r"(r[1]), "=r"(r[2]), "=r"(r[3]) : "r"(addr));
}

__device__ __forceinline__ void mma16816(float c[4], const uint32_t a[4], const uint32_t b[2]) {
    asm volatile(
        "mma.sync.aligned.m16n8k16.row.col.f32.bf16.bf16.f32 "
        "{%0,%1,%2,%3}, {%4,%5,%6,%7}, {%8,%9}, {%0,%1,%2,%3};"
        : "+f"(c[0]), "+f"(c[1]), "+f"(c[2]), "+f"(c[3])
        : "r"(a[0]), "r"(a[1]), "r"(a[2]), "r"(a[3]), "r"(b[0]), "r"(b[1]));
}

// ---------------------------------------------------------------------------
// Fused attention core: per (b,h) and 128-row strip:
//   expP = exp(alpha * Q K^T)  -> written unnormalized, then re-read and
//   normalized IN-PLACE by this CTA once its full row sums are known.
//   O = (expP @ V) * (1/rowsum) -> written to O.
// 8 warps, each owns 16 rows x full 128-col tile; P fragments reused in regs
// as A-operand of the PV MMA (accumulator layout == A-fragment layout).
// ---------------------------------------------------------------------------
__global__ void __launch_bounds__(256, 1) attn_fused(
    const float* __restrict__ Q, const float* __restrict__ Kp,
    const float* __restrict__ VT, float* __restrict__ P,
    float* __restrict__ O, float alpha)
{
    constexpr int PITCH  = 144;               // Q/K rows: 128B bf16 + 16B pad
    constexpr int PLANE  = 128 * PITCH;       // 18432
    constexpr int VPITCH = 272;               // VT rows: 256B bf16 + 16B pad
    constexpr int VPLANE = 64 * VPITCH;       // 17408
    constexpr int KOFF   = 2 * PLANE;         // 36864
    constexpr int VOFF   = KOFF + 4 * PLANE;  // 110592 (2 K stages x hi/lo)
    extern __shared__ char smem[];
    const uint32_t sb = smem_u32(smem);

    const int z = blockIdx.z;                  // b*NH + h
    const int b = z / NH, h = z % NH;
    const int brow = blockIdx.y * 128;
    const float* Aq = Q  + (long)b * SEQ * DM + (long)h * HD;
    const float* Bk = Kp + (long)b * SEQ * DM + (long)h * HD;
    const float* Vt = VT + (long)z * HD * SEQ;
    float* C = P + (long)z * SEQ * SEQ;

    const int tid = threadIdx.x, lane = tid & 31, wid = tid >> 5;
    const int g = lane >> 3;
    const int lrow = (lane & 7) + ((g & 1) << 3);
    const int lc16 = (g >> 1) << 4;
    const int gr = lane >> 2, qc = (lane & 3) * 2;

    // ---- load + split Q strip (128 x 64) once
#pragma unroll
    for (int i = 0; i < 8; i++) {
        int f = tid + i * 256, r = f >> 4, fi = f & 15;
        float4 v = *reinterpret_cast<const float4*>(Aq + (long)(brow + r) * DM + fi * 4);
        uint32_t h0, l0, h1, l1;
        split2(v.x, v.y, h0, l0); split2(v.z, v.w, h1, l1);
        *reinterpret_cast<uint2*>(smem + r * PITCH + fi * 8)         = make_uint2(h0, h1);
        *reinterpret_cast<uint2*>(smem + PLANE + r * PITCH + fi * 8) = make_uint2(l0, l1);
    }
    // ---- K tile 0 -> K stage 0
#pragma unroll
    for (int i = 0; i < 8; i++) {
        int f = tid + i * 256, r = f >> 4, fi = f & 15;
        float4 v = *reinterpret_cast<const float4*>(Bk + (long)r * DM + fi * 4);
        uint32_t h0, l0, h1, l1;
        split2(v.x, v.y, h0, l0); split2(v.z, v.w, h1, l1);
        *reinterpret_cast<uint2*>(smem + KOFF + r * PITCH + fi * 8)         = make_uint2(h0, h1);
        *reinterpret_cast<uint2*>(smem + KOFF + PLANE + r * PITCH + fi * 8) = make_uint2(l0, l1);
    }
    // ---- VT tile 0 (64 x 128) -> V stage 0
#pragma unroll
    for (int i = 0; i < 8; i++) {
        int f = tid + i * 256, r = f >> 5, fi = f & 31;
        float4 v = *reinterpret_cast<const float4*>(Vt + (long)r * SEQ + fi * 4);
        uint32_t h0, l0, h1, l1;
        split2(v.x, v.y, h0, l0); split2(v.z, v.w, h1, l1);
        *reinterpret_cast<uint2*>(smem + VOFF + r * VPITCH + fi * 8)          = make_uint2(h0, h1);
        *reinterpret_cast<uint2*>(smem + VOFF + VPLANE + r * VPITCH + fi * 8) = make_uint2(l0, l1);
    }

    float o_acc[8][4];
#pragma unroll
    for (int i = 0; i < 8; i++)
#pragma unroll
        for (int j = 0; j < 4; j++) o_acc[i][j] = 0.0f;
    float rs0 = 0.0f, rs1 = 0.0f;
    float4 pf[8];

    for (int ct = 0; ct < 16; ++ct) {
        __syncthreads();
        const int buf = ct & 1;

        // prefetch K(ct+1) to regs
        if (ct < 15) {
            const float* Bn = Bk + (long)(ct + 1) * 128 * DM;
#pragma unroll
            for (int i = 0; i < 8; i++) {
                int f = tid + i * 256, r = f >> 4, fi = f & 15;
                pf[i] = *reinterpret_cast<const float4*>(Bn + (long)r * DM + fi * 4);
            }
        }

        // ---- scores: acc(16x128) = Q_w(16x64) @ K_tile(128x64)^T, 3-term split
        float acc[16][4];
#pragma unroll
        for (int i = 0; i < 16; i++)
#pragma unroll
            for (int j = 0; j < 4; j++) acc[i][j] = 0.0f;

        const uint32_t kHi = sb + KOFF + (uint32_t)buf * 2 * PLANE;
        const uint32_t kLo = kHi + PLANE;
#pragma unroll
        for (int kg = 0; kg < 4; kg++) {
            const int kb = kg * 32 + lc16;
            uint32_t a_h[4], a_l[4];
            int r0 = wid * 16 + lrow;
            ldm4(sb + r0 * PITCH + kb, a_h);
            ldm4(sb + PLANE + r0 * PITCH + kb, a_l);
#pragma unroll
            for (int np = 0; np < 8; np++) {
                int n0 = np * 16 + lrow;
                uint32_t th[4], tl[4];
                ldm4(kHi + n0 * PITCH + kb, th);
                ldm4(kLo + n0 * PITCH + kb, tl);
                uint32_t bh0[2] = {th[0], th[2]}, bh1[2] = {th[1], th[3]};
                uint32_t bl0[2] = {tl[0], tl[2]}, bl1[2] = {tl[1], tl[3]};
                mma16816(acc[2*np],     a_h, bh0);
                mma16816(acc[2*np],     a_h, bl0);
                mma16816(acc[2*np],     a_l, bh0);
                mma16816(acc[2*np + 1], a_h, bh1);
                mma16816(acc[2*np + 1], a_h, bl1);
                mma16816(acc[2*np + 1], a_l, bh1);
            }
        }

        // store K prefetch into other stage; then prefetch VT(ct+1)
        if (ct < 15) {
            char* st = smem + KOFF + (buf ^ 1) * 2 * PLANE;
#pragma unroll
            for (int i = 0; i < 8; i++) {
                int f = tid + i * 256, r = f >> 4, fi = f & 15;
                uint32_t h0, l0, h1, l1;
                split2(pf[i].x, pf[i].y, h0, l0); split2(pf[i].z, pf[i].w, h1, l1);
                *reinterpret_cast<uint2*>(st + r * PITCH + fi * 8)         = make_uint2(h0, h1);
                *reinterpret_cast<uint2*>(st + PLANE + r * PITCH + fi * 8) = make_uint2(l0, l1);
            }
            const float* Vn = Vt + (ct + 1) * 128;
#pragma unroll
            for (int i = 0; i < 8; i++) {
                int f = tid + i * 256, r = f >> 5, fi = f & 31;
                pf[i] = *reinterpret_cast<const float4*>(Vn + (long)r * SEQ + fi * 4);
            }
        }

        // ---- exp + P store + register A-frag conversion + PV MMA
        const uint32_t vHi = sb + VOFF + (uint32_t)buf * 2 * VPLANE;
        const uint32_t vLo = vHi + VPLANE;
        const long rowg = brow + wid * 16 + gr;
#pragma unroll
        for (int kk = 0; kk < 8; kk++) {
            float e00 = __expf(alpha * acc[2*kk][0]), e01 = __expf(alpha * acc[2*kk][1]);
            float e02 = __expf(alpha * acc[2*kk][2]), e03 = __expf(alpha * acc[2*kk][3]);
            float e10 = __expf(alpha * acc[2*kk+1][0]), e11 = __expf(alpha * acc[2*kk+1][1]);
            float e12 = __expf(alpha * acc[2*kk+1][2]), e13 = __expf(alpha * acc[2*kk+1][3]);
            rs0 += (e00 + e01) + (e10 + e11);
            rs1 += (e02 + e03) + (e12 + e13);
            long col = (long)ct * 128 + kk * 16 + qc;
            *reinterpret_cast<float2*>(C + rowg * SEQ + col)           = make_float2(e00, e01);
            *reinterpret_cast<float2*>(C + (rowg + 8) * SEQ + col)     = make_float2(e02, e03);
            *reinterpret_cast<float2*>(C + rowg * SEQ + col + 8)       = make_float2(e10, e11);
            *reinterpret_cast<float2*>(C + (rowg + 8) * SEQ + col + 8) = make_float2(e12, e13);

            uint32_t pa_h[4], pa_l[4];
            split2(e00, e01, pa_h[0], pa_l[0]);
            split2(e02, e03, pa_h[1], pa_l[1]);
            split2(e10, e11, pa_h[2], pa_l[2]);
            split2(e12, e13, pa_h[3], pa_l[3]);

            const int vb = kk * 32 + lc16;
#pragma unroll
            for (int np2 = 0; np2 < 4; np2++) {
                int n0 = np2 * 16 + lrow;
                uint32_t th[4], tl[4];
                ldm4(vHi + n0 * VPITCH + vb, th);
                ldm4(vLo + n0 * VPITCH + vb, tl);
                uint32_t bh0[2] = {th[0], th[2]}, bh1[2] = {th[1], th[3]};
                uint32_t bl0[2] = {tl[0], tl[2]}, bl1[2] = {tl[1], tl[3]};
                mma16816(o_acc[2*np2],     pa_h, bh0);
                mma16816(o_acc[2*np2],     pa_h, bl0);
                mma16816(o_acc[2*np2],     pa_l, bh0);
                mma16816(o_acc[2*np2 + 1], pa_h, bh1);
                mma16816(o_acc[2*np2 + 1], pa_h, bl1);
                mma16816(o_acc[2*np2 + 1], pa_l, bh1);
            }
        }

        // store VT prefetch into other stage
        if (ct < 15) {
            char* st = smem + VOFF + (buf ^ 1) * 2 * VPLANE;
#pragma unroll
            for (int i = 0; i < 8; i++) {
                int f = tid + i * 256, r = f >> 5, fi = f & 31;
                uint32_t h0, l0, h1, l1;
                split2(pf[i].x, pf[i].y, h0, l0); split2(pf[i].z, pf[i].w, h1, l1);
                *reinterpret_cast<uint2*>(st + r * VPITCH + fi * 8)          = make_uint2(h0, h1);
                *reinterpret_cast<uint2*>(st + VPLANE + r * VPITCH + fi * 8) = make_uint2(l0, l1);
            }
        }
    }

    // ---- row sums (deterministic) -> invert in smem
    __syncthreads();
    float* ps = reinterpret_cast<float*>(smem + KOFF);
    {
        float v0 = rs0;
        v0 += __shfl_xor_sync(0xffffffffu, v0, 1);
        v0 += __shfl_xor_sync(0xffffffffu, v0, 2);
        float v1 = rs1;
        v1 += __shfl_xor_sync(0xffffffffu, v1, 1);
        v1 += __shfl_xor_sync(0xffffffffu, v1, 2);
        if ((lane & 3) == 0) {
            ps[wid * 16 + gr]     = v0;
            ps[wid * 16 + gr + 8] = v1;
        }
    }
    __syncthreads();
    if (tid < 128) ps[tid] = 1.0f / ps[tid];
    __syncthreads();

    // ---- O normalize + store
    float inv0 = ps[wid * 16 + gr];
    float inv1 = ps[wid * 16 + gr + 8];
    float* Og = O + ((long)b * SEQ + brow + wid * 16) * DM + h * HD;
#pragma unroll
    for (int nt2 = 0; nt2 < 8; nt2++) {
        int col = nt2 * 8 + qc;
        *reinterpret_cast<float2*>(Og + (long)gr * DM + col) =
            make_float2(o_acc[nt2][0] * inv0, o_acc[nt2][1] * inv0);
        *reinterpret_cast<float2*>(Og + (long)(gr + 8) * DM + col) =
            make_float2(o_acc[nt2][2] * inv1, o_acc[nt2][3] * inv1);
    }

    // ---- normalize this CTA's P strip in-place (128 rows x 2048 cols)
    // Writes above were by this CTA; __syncthreads orders gmem within the CTA.
    float4* Cs = reinterpret_cast<float4*>(C + (long)brow * SEQ);
#pragma unroll 4
    for (int i = 0; i < 256; i++) {
        int idx = i * 256 + tid;
        float iv = ps[idx >> 9];           // 512 float4 per row
        float4 v = Cs[idx];
        v.x *= iv; v.y *= iv; v.z *= iv; v.w *= iv;
        Cs[idx] = v;
    }
}

// ---------------------------------------------------------------------------
// NT GEMM via mma.sync bf16, 3-term split: C = A[M,K] @ B[N,K]^T
// MODE 0: plain store. MODE 3: transposed store per head -> vt[bh][d][s]
// (smem bounce; used for the V projection). BM=BN=128, BK=32. 256 threads.
// ---------------------------------------------------------------------------
template<int MODE>
__global__ void __launch_bounds__(256, 1) gemm_nt_mma(
    const float* __restrict__ A, const float* __restrict__ B, float* __restrict__ C,
    int K, int lda, int ldb, int ldc)
{
    constexpr int BM = 128, BN = 128, BK = 32;
    constexpr int ROWB = 80;
    constexpr int A_PLANE = BM * ROWB;
    constexpr int B_PLANE = BN * ROWB;
    constexpr int STAGE = 2 * A_PLANE + 2 * B_PLANE;

    extern __shared__ char smem[];
    const uint32_t sb = smem_u32(smem);

    const int tid = threadIdx.x, lane = tid & 31, wid = tid >> 5;
    const int wm = wid & 1, wn = wid >> 1;
    const int brow = blockIdx.y * BM;
    const int bcol = blockIdx.x * BN;

    float acc[4][4][4];
#pragma unroll
    for (int i = 0; i < 4; i++)
#pragma unroll
        for (int j = 0; j < 4; j++)
#pragma unroll
            for (int r = 0; r < 4; r++) acc[i][j][r] = 0.0f;

    float4 va[4], vb[4];
    const int nc = K / BK;

    const int g = lane >> 3;
    const int lrow = (lane & 7) + ((g & 1) << 3);
    const int lc16 = (g >> 1) << 4;

    // prologue: chunk 0 -> buffer 0
    {
#pragma unroll
        for (int i = 0; i < 4; i++) {
            int f = tid + i * 256, r = f >> 3, fi = f & 7;
            va[i] = *reinterpret_cast<const float4*>(A + (long)(brow + r) * lda + fi * 4);
            vb[i] = *reinterpret_cast<const float4*>(B + (long)(bcol + r) * ldb + fi * 4);
        }
        char* st = smem;
#pragma unroll
        for (int i = 0; i < 4; i++) {
            int f = tid + i * 256, r = f >> 3, fi = f & 7;
            uint32_t h0, l0, h1, l1;
            split2(va[i].x, va[i].y, h0, l0); split2(va[i].z, va[i].w, h1, l1);
            *reinterpret_cast<uint2*>(st + r * ROWB + fi * 8)           = make_uint2(h0, h1);
            *reinterpret_cast<uint2*>(st + A_PLANE + r * ROWB + fi * 8) = make_uint2(l0, l1);
            split2(vb[i].x, vb[i].y, h0, l0); split2(vb[i].z, vb[i].w, h1, l1);
            *reinterpret_cast<uint2*>(st + 2 * A_PLANE + r * ROWB + fi * 8)           = make_uint2(h0, h1);
            *reinterpret_cast<uint2*>(st + 2 * A_PLANE + B_PLANE + r * ROWB + fi * 8) = make_uint2(l0, l1);
        }
    }

    for (int c = 0; c < nc; ++c) {
        __syncthreads();
        const int buf = c & 1;

        if (c + 1 < nc) {
            const int k0 = (c + 1) * BK;
#pragma unroll
            for (int i = 0; i < 4; i++) {
                int f = tid + i * 256, r = f >> 3, fi = f & 7;
                va[i] = *reinterpret_cast<const float4*>(A + (long)(brow + r) * lda + k0 + fi * 4);
                vb[i] = *reinterpret_cast<const float4*>(B + (long)(bcol + r) * ldb + k0 + fi * 4);
            }
        }

        {
            const uint32_t aHi = sb + buf * STAGE;
            const uint32_t aLo = aHi + A_PLANE;
            const uint32_t bHi = aHi + 2 * A_PLANE;
            const uint32_t bLo = bHi + B_PLANE;
#pragma unroll
            for (int kg = 0; kg < 2; kg++) {
                const int kb = kg * 32 + lc16;
                uint32_t a_h[4][4], a_l[4][4];
#pragma unroll
                for (int mt = 0; mt < 4; mt++) {
                    int r0 = wm * 64 + mt * 16 + lrow;
                    ldm4(aHi + r0 * ROWB + kb, a_h[mt]);
                    ldm4(aLo + r0 * ROWB + kb, a_l[mt]);
                }
                uint32_t b_h[4][2], b_l[4][2];
#pragma unroll
                for (int np = 0; np < 2; np++) {
                    int n0 = wn * 32 + np * 16 + lrow;
                    uint32_t t[4];
                    ldm4(bHi + n0 * ROWB + kb, t);
                    b_h[2*np][0] = t[0]; b_h[2*np+1][0] = t[1];
                    b_h[2*np][1] = t[2]; b_h[2*np+1][1] = t[3];
                    ldm4(bLo + n0 * ROWB + kb, t);
                    b_l[2*np][0] = t[0]; b_l[2*np+1][0] = t[1];
                    b_l[2*np][1] = t[2]; b_l[2*np+1][1] = t[3];
                }
#pragma unroll
                for (int mt = 0; mt < 4; mt++)
#pragma unroll
                    for (int nt = 0; nt < 4; nt++) {
                        mma16816(acc[mt][nt], a_h[mt], b_h[nt]);
                        mma16816(acc[mt][nt], a_h[mt], b_l[nt]);
                        mma16816(acc[mt][nt], a_l[mt], b_h[nt]);
                    }
            }
        }

        if (c + 1 < nc) {
            char* st = smem + (buf ^ 1) * STAGE;
#pragma unroll
            for (int i = 0; i < 4; i++) {
                int f = tid + i * 256, r = f >> 3, fi = f & 7;
                uint32_t h0, l0, h1, l1;
                split2(va[i].x, va[i].y, h0, l0); split2(va[i].z, va[i].w, h1, l1);
                *reinterpret_cast<uint2*>(st + r * ROWB + fi * 8)           = make_uint2(h0, h1);
                *reinterpret_cast<uint2*>(st + A_PLANE + r * ROWB + fi * 8) = make_uint2(l0, l1);
                split2(vb[i].x, vb[i].y, h0, l0); split2(vb[i].z, vb[i].w, h1, l1);
                *reinterpret_cast<uint2*>(st + 2 * A_PLANE + r * ROWB + fi * 8)           = make_uint2(h0, h1);
                *reinterpret_cast<uint2*>(st + 2 * A_PLANE + B_PLANE + r * ROWB + fi * 8) = make_uint2(l0, l1);
            }
        }
    }

    if (MODE == 0) {
#pragma unroll
        for (int mt = 0; mt < 4; mt++)
#pragma unroll
            for (int nt = 0; nt < 4; nt++) {
                long row = brow + wm * 64 + mt * 16 + (lane >> 2);
                long col = bcol + wn * 32 + nt * 8 + (lane & 3) * 2;
                *reinterpret_cast<float2*>(C + row * ldc + col) =
                    make_float2(acc[mt][nt][0], acc[mt][nt][1]);
                *reinterpret_cast<float2*>(C + (row + 8) * ldc + col) =
                    make_float2(acc[mt][nt][2], acc[mt][nt][3]);
            }
    } else {
        // MODE 3: transpose via smem, write vt[bh][d][s] (C = vt base)
        constexpr int TP = 132;                      // fp32 pitch, float4-aligned
        __syncthreads();
        float* tb = reinterpret_cast<float*>(smem);  // [128 d][132 s]
#pragma unroll
        for (int mt = 0; mt < 4; mt++)
#pragma unroll
            for (int nt = 0; nt < 4; nt++) {
                int s0 = wm * 64 + mt * 16 + (lane >> 2);
                int d0 = wn * 32 + nt * 8 + (lane & 3) * 2;
                tb[d0 * TP + s0]           = acc[mt][nt][0];
                tb[(d0 + 1) * TP + s0]     = acc[mt][nt][1];
                tb[d0 * TP + s0 + 8]       = acc[mt][nt][2];
                tb[(d0 + 1) * TP + s0 + 8] = acc[mt][nt][3];
            }
        __syncthreads();
        const int bb = brow >> 11;          // batch
        const int srow0 = brow & 2047;
        const int h0 = bcol >> 6;           // first of 2 heads in this col block
#pragma unroll
        for (int i = 0; i < 16; i++) {
            int f = tid + i * 256;
            int d = f >> 5, s = (f & 31) * 4;
            float4 v = *reinterpret_cast<float4*>(&tb[d * TP + s]);
            int hh = h0 + (d >> 6), dd = d & 63;
            *reinterpret_cast<float4*>(
                C + ((long)(bb * NH + hh) * HD + dd) * SEQ + srow0 + s) = v;
        }
    }
}

// ---------------------------------------------------------------------------
extern "C" void kernel_launch(void* const* d_in, const int* in_sizes, int n_in,
                              void* d_out, int out_size)
{
    const float* x  = (const float*)d_in[0];
    const float* Wq = (const float*)d_in[1];
    const float* Wk = (const float*)d_in[2];
    const float* Wv = (const float*)d_in[3];
    const float* Wo = (const float*)d_in[4];
    float* out = (float*)d_out;

    float *q, *k, *vt, *o;
    cudaGetSymbolAddress((void**)&q,  g_q);
    cudaGetSymbolAddress((void**)&k,  g_k);
    cudaGetSymbolAddress((void**)&vt, g_vt);
    cudaGetSymbolAddress((void**)&o,  g_o);

    const long OUT_ELEMS = (long)MTOT * DM;      // 4194304
    float* attn = out + OUT_ELEMS;               // verified layout

    constexpr int SMEMG = 2 * (2 * 128 * 80 + 2 * 128 * 80);  // 81920
    constexpr int SMEMF = 110592 + 2 * 2 * 17408;             // 180224
    cudaFuncSetAttribute(gemm_nt_mma<0>, cudaFuncAttributeMaxDynamicSharedMemorySize, SMEMG);
    cudaFuncSetAttribute(gemm_nt_mma<3>, cudaFuncAttributeMaxDynamicSharedMemorySize, SMEMG);
    cudaFuncSetAttribute(attn_fused,     cudaFuncAttributeMaxDynamicSharedMemorySize, SMEMF);

    const float scale = 0.125f;  // 1/sqrt(64)
    dim3 thr(256);
    dim3 gproj(DM / 128, MTOT / 128, 1);

    // 0) V projection with transposed store -> vt
    gemm_nt_mma<3><<<gproj, thr, SMEMG>>>(x, Wv, vt, DM, DM, DM, DM);
    // 1-2) Q/K projections
    gemm_nt_mma<0><<<gproj, thr, SMEMG>>>(x, Wq, q, DM, DM, DM, DM);
    gemm_nt_mma<0><<<gproj, thr, SMEMG>>>(x, Wk, k, DM, DM, DM, DM);

    // 3) fused: expP + row sums + in-place normalize + O  [profiled slot]
    dim3 gf(1, SEQ / 128, NB * NH);
    attn_fused<<<gf, thr, SMEMF>>>(q, k, vt, attn, o, scale);

    // 4) out = O @ Wo^T
    gemm_nt_mma<0><<<gproj, thr, SMEMG>>>(o, Wo, out, DM, DM, DM, DM);
}

// round 12
// speedup vs baseline: 1.0486x; 1.0486x over previous
#include <cuda_runtime.h>
#include <cuda_bf16.h>
#include <cstdint>

#define NB   2
#define SEQ  2048
#define DM   1024
#define NH   16
#define HD   64
#define MTOT (NB*SEQ)   // 4096

// Scratch (static device globals — allocation-free per harness rules)
__device__ float g_q[MTOT * DM];
__device__ float g_k[MTOT * DM];
__device__ float g_vt[NB * NH * HD * SEQ];     // V^T per (b,h): [HD][SEQ]
__device__ float g_o[MTOT * DM];
__device__ float g_pinv[(long)NB * NH * SEQ];  // per-row INVERSE exp sums

// ---------------------------------------------------------------------------
// helpers
// ---------------------------------------------------------------------------
__device__ __forceinline__ uint32_t smem_u32(const void* p) {
    uint32_t a;
    asm("{ .reg .u64 t; cvta.to.shared.u64 t, %1; cvt.u32.u64 %0, t; }"
        : "=r"(a) : "l"(p));
    return a;
}

// 3-term bf16 split: x = hi + lo (hi = bf16(x), lo = bf16(x - hi)).
__device__ __forceinline__ void split2(float x, float y, uint32_t& hi, uint32_t& lo) {
    __nv_bfloat16 hx = __float2bfloat16_rn(x);
    __nv_bfloat16 hy = __float2bfloat16_rn(y);
    float rx = x - __bfloat162float(hx);
    float ry = y - __bfloat162float(hy);
    __nv_bfloat16 lx = __float2bfloat16_rn(rx);
    __nv_bfloat16 ly = __float2bfloat16_rn(ry);
    hi = ((uint32_t)__bfloat16_as_ushort(hy) << 16) | (uint32_t)__bfloat16_as_ushort(hx);
    lo = ((uint32_t)__bfloat16_as_ushort(ly) << 16) | (uint32_t)__bfloat16_as_ushort(lx);
}

__device__ __forceinline__ void ldm4(uint32_t addr, uint32_t r[4]) {
    asm volatile("ldmatrix.sync.aligned.m8n8.x4.shared.b16 {%0,%1,%2,%3}, [%4];"
                 : "=r"(r[0]), "=r"(r[1]), "=r"(r[2]), "=r"(r[3]) : "r"(addr));
}

__device__ __forceinline__ void mma16816(float c[4], const uint32_t a[4], const uint32_t b[2]) {
    asm volatile(
        "mma.sync.aligned.m16n8k16.row.col.f32.bf16.bf16.f32 "
        "{%0,%1,%2,%3}, {%4,%5,%6,%7}, {%8,%9}, {%0,%1,%2,%3};"
        : "+f"(c[0]), "+f"(c[1]), "+f"(c[2]), "+f"(c[3])
        : "r"(a[0]), "r"(a[1]), "r"(a[2]), "r"(a[3]), "r"(b[0]), "r"(b[1]));
}

// ---------------------------------------------------------------------------
// Fused attention core, 512 threads = 16 warps. Per (b,h) and 128-row strip:
//   expP = exp(alpha * Q K^T) -> written unnormalized to P (attn region)
//   pinv[row] = 1 / full row sum -> gmem (for the normalize pass)
//   O = (expP @ V) * pinv      -> written to O
// Warp wid: row group (wid&7)*16, column half (wid>>3)*64 of each 128-col tile.
// P fragments reused in regs as A-operand of the PV MMA. The two column-half
// warps hold partial O over disjoint k-ranges -> smem reduction at the end.
// ---------------------------------------------------------------------------
__global__ void __launch_bounds__(512, 1) attn_fused(
    const float* __restrict__ Q, const float* __restrict__ Kp,
    const float* __restrict__ VT, float* __restrict__ P,
    float* __restrict__ O, float* __restrict__ pinv, float alpha)
{
    constexpr int PITCH  = 144;               // Q/K rows: 128B bf16 + 16B pad
    constexpr int PLANE  = 128 * PITCH;       // 18432
    constexpr int VPITCH = 272;               // VT rows: 256B bf16 + 16B pad
    constexpr int VPLANE = 64 * VPITCH;       // 17408
    constexpr int KOFF   = 2 * PLANE;         // 36864
    constexpr int VOFF   = KOFF + 4 * PLANE;  // 110592
    extern __shared__ char smem[];
    const uint32_t sb = smem_u32(smem);

    const int z = blockIdx.z;                  // b*NH + h
    const int b = z / NH, h = z % NH;
    const int brow = blockIdx.y * 128;
    const float* Aq = Q  + (long)b * SEQ * DM + (long)h * HD;
    const float* Bk = Kp + (long)b * SEQ * DM + (long)h * HD;
    const float* Vt = VT + (long)z * HD * SEQ;
    float* C = P + (long)z * SEQ * SEQ;

    const int tid = threadIdx.x, lane = tid & 31, wid = tid >> 5;
    const int rw = wid & 7;                    // row group (16 rows)
    const int ch = wid >> 3;                   // column half (64 cols)
    const int g = lane >> 3;
    const int lrow = (lane & 7) + ((g & 1) << 3);
    const int lc16 = (g >> 1) << 4;
    const int gr = lane >> 2, qc = (lane & 3) * 2;

    // ---- load + split Q strip (128 x 64) once: 4 x 512 float4
#pragma unroll
    for (int i = 0; i < 4; i++) {
        int f = tid + i * 512, r = f >> 4, fi = f & 15;
        float4 v = *reinterpret_cast<const float4*>(Aq + (long)(brow + r) * DM + fi * 4);
        uint32_t h0, l0, h1, l1;
        split2(v.x, v.y, h0, l0); split2(v.z, v.w, h1, l1);
        *reinterpret_cast<uint2*>(smem + r * PITCH + fi * 8)         = make_uint2(h0, h1);
        *reinterpret_cast<uint2*>(smem + PLANE + r * PITCH + fi * 8) = make_uint2(l0, l1);
    }
    // ---- K tile 0 -> K stage 0
#pragma unroll
    for (int i = 0; i < 4; i++) {
        int f = tid + i * 512, r = f >> 4, fi = f & 15;
        float4 v = *reinterpret_cast<const float4*>(Bk + (long)r * DM + fi * 4);
        uint32_t h0, l0, h1, l1;
        split2(v.x, v.y, h0, l0); split2(v.z, v.w, h1, l1);
        *reinterpret_cast<uint2*>(smem + KOFF + r * PITCH + fi * 8)         = make_uint2(h0, h1);
        *reinterpret_cast<uint2*>(smem + KOFF + PLANE + r * PITCH + fi * 8) = make_uint2(l0, l1);
    }
    // ---- VT tile 0 (64 x 128) -> V stage 0
#pragma unroll
    for (int i = 0; i < 4; i++) {
        int f = tid + i * 512, r = f >> 5, fi = f & 31;
        float4 v = *reinterpret_cast<const float4*>(Vt + (long)r * SEQ + fi * 4);
        uint32_t h0, l0, h1, l1;
        split2(v.x, v.y, h0, l0); split2(v.z, v.w, h1, l1);
        *reinterpret_cast<uint2*>(smem + VOFF + r * VPITCH + fi * 8)          = make_uint2(h0, h1);
        *reinterpret_cast<uint2*>(smem + VOFF + VPLANE + r * VPITCH + fi * 8) = make_uint2(l0, l1);
    }

    float o_acc[8][4];
#pragma unroll
    for (int i = 0; i < 8; i++)
#pragma unroll
        for (int j = 0; j < 4; j++) o_acc[i][j] = 0.0f;
    float rs0 = 0.0f, rs1 = 0.0f;
    float4 pf[4];

    for (int ct = 0; ct < 16; ++ct) {
        __syncthreads();
        const int buf = ct & 1;

        // prefetch K(ct+1) to regs
        if (ct < 15) {
            const float* Bn = Bk + (long)(ct + 1) * 128 * DM;
#pragma unroll
            for (int i = 0; i < 4; i++) {
                int f = tid + i * 512, r = f >> 4, fi = f & 15;
                pf[i] = *reinterpret_cast<const float4*>(Bn + (long)r * DM + fi * 4);
            }
        }

        // ---- scores: acc(16x64) = Q_w(16x64) @ K_half(64x64)^T, 3-term split
        float acc[8][4];
#pragma unroll
        for (int i = 0; i < 8; i++)
#pragma unroll
            for (int j = 0; j < 4; j++) acc[i][j] = 0.0f;

        const uint32_t kHi = sb + KOFF + (uint32_t)buf * 2 * PLANE;
        const uint32_t kLo = kHi + PLANE;
#pragma unroll
        for (int kg = 0; kg < 4; kg++) {
            const int kb = kg * 32 + lc16;
            uint32_t a_h[4], a_l[4];
            int r0 = rw * 16 + lrow;
            ldm4(sb + r0 * PITCH + kb, a_h);
            ldm4(sb + PLANE + r0 * PITCH + kb, a_l);
#pragma unroll
            for (int np = 0; np < 4; np++) {
                int n0 = ch * 64 + np * 16 + lrow;
                uint32_t th[4], tl[4];
                ldm4(kHi + n0 * PITCH + kb, th);
                ldm4(kLo + n0 * PITCH + kb, tl);
                uint32_t bh0[2] = {th[0], th[2]}, bh1[2] = {th[1], th[3]};
                uint32_t bl0[2] = {tl[0], tl[2]}, bl1[2] = {tl[1], tl[3]};
                mma16816(acc[2*np],     a_h, bh0);
                mma16816(acc[2*np],     a_h, bl0);
                mma16816(acc[2*np],     a_l, bh0);
                mma16816(acc[2*np + 1], a_h, bh1);
                mma16816(acc[2*np + 1], a_h, bl1);
                mma16816(acc[2*np + 1], a_l, bh1);
            }
        }

        // store K prefetch into other stage; then prefetch VT(ct+1)
        if (ct < 15) {
            char* st = smem + KOFF + (buf ^ 1) * 2 * PLANE;
#pragma unroll
            for (int i = 0; i < 4; i++) {
                int f = tid + i * 512, r = f >> 4, fi = f & 15;
                uint32_t h0, l0, h1, l1;
                split2(pf[i].x, pf[i].y, h0, l0); split2(pf[i].z, pf[i].w, h1, l1);
                *reinterpret_cast<uint2*>(st + r * PITCH + fi * 8)         = make_uint2(h0, h1);
                *reinterpret_cast<uint2*>(st + PLANE + r * PITCH + fi * 8) = make_uint2(l0, l1);
            }
            const float* Vn = Vt + (ct + 1) * 128;
#pragma unroll
            for (int i = 0; i < 4; i++) {
                int f = tid + i * 512, r = f >> 5, fi = f & 31;
                pf[i] = *reinterpret_cast<const float4*>(Vn + (long)r * SEQ + fi * 4);
            }
        }

        // ---- exp + P store + register A-frag conversion + PV MMA
        const uint32_t vHi = sb + VOFF + (uint32_t)buf * 2 * VPLANE;
        const uint32_t vLo = vHi + VPLANE;
        const long rowg = brow + rw * 16 + gr;
#pragma unroll
        for (int kk = 0; kk < 4; kk++) {
            float e00 = __expf(alpha * acc[2*kk][0]), e01 = __expf(alpha * acc[2*kk][1]);
            float e02 = __expf(alpha * acc[2*kk][2]), e03 = __expf(alpha * acc[2*kk][3]);
            float e10 = __expf(alpha * acc[2*kk+1][0]), e11 = __expf(alpha * acc[2*kk+1][1]);
            float e12 = __expf(alpha * acc[2*kk+1][2]), e13 = __expf(alpha * acc[2*kk+1][3]);
            rs0 += (e00 + e01) + (e10 + e11);
            rs1 += (e02 + e03) + (e12 + e13);
            long col = (long)ct * 128 + ch * 64 + kk * 16 + qc;
            *reinterpret_cast<float2*>(C + rowg * SEQ + col)           = make_float2(e00, e01);
            *reinterpret_cast<float2*>(C + (rowg + 8) * SEQ + col)     = make_float2(e02, e03);
            *reinterpret_cast<float2*>(C + rowg * SEQ + col + 8)       = make_float2(e10, e11);
            *reinterpret_cast<float2*>(C + (rowg + 8) * SEQ + col + 8) = make_float2(e12, e13);

            uint32_t pa_h[4], pa_l[4];
            split2(e00, e01, pa_h[0], pa_l[0]);
            split2(e02, e03, pa_h[1], pa_l[1]);
            split2(e10, e11, pa_h[2], pa_l[2]);
            split2(e12, e13, pa_h[3], pa_l[3]);

            const int vb = ch * 128 + kk * 32 + lc16;
#pragma unroll
            for (int np2 = 0; np2 < 4; np2++) {
                int n0 = np2 * 16 + lrow;
                uint32_t th[4], tl[4];
                ldm4(vHi + n0 * VPITCH + vb, th);
                ldm4(vLo + n0 * VPITCH + vb, tl);
                uint32_t bh0[2] = {th[0], th[2]}, bh1[2] = {th[1], th[3]};
                uint32_t bl0[2] = {tl[0], tl[2]}, bl1[2] = {tl[1], tl[3]};
                mma16816(o_acc[2*np2],     pa_h, bh0);
                mma16816(o_acc[2*np2],     pa_h, bl0);
                mma16816(o_acc[2*np2],     pa_l, bh0);
                mma16816(o_acc[2*np2 + 1], pa_h, bh1);
                mma16816(o_acc[2*np2 + 1], pa_h, bl1);
                mma16816(o_acc[2*np2 + 1], pa_l, bh1);
            }
        }

        // store VT prefetch into other stage
        if (ct < 15) {
            char* st = smem + VOFF + (buf ^ 1) * 2 * VPLANE;
#pragma unroll
            for (int i = 0; i < 4; i++) {
                int f = tid + i * 512, r = f >> 5, fi = f & 31;
                uint32_t h0, l0, h1, l1;
                split2(pf[i].x, pf[i].y, h0, l0); split2(pf[i].z, pf[i].w, h1, l1);
                *reinterpret_cast<uint2*>(st + r * VPITCH + fi * 8)          = make_uint2(h0, h1);
                *reinterpret_cast<uint2*>(st + VPLANE + r * VPITCH + fi * 8) = make_uint2(l0, l1);
            }
        }
    }

    // ---- row sums: combine halves (deterministic), invert, write pinv
    __syncthreads();
    float* ps  = reinterpret_cast<float*>(smem + KOFF);          // [128][2]
    float* inv = reinterpret_cast<float*>(smem + KOFF + 1024);   // [128]
    {
        float v0 = rs0;
        v0 += __shfl_xor_sync(0xffffffffu, v0, 1);
        v0 += __shfl_xor_sync(0xffffffffu, v0, 2);
        float v1 = rs1;
        v1 += __shfl_xor_sync(0xffffffffu, v1, 1);
        v1 += __shfl_xor_sync(0xffffffffu, v1, 2);
        if ((lane & 3) == 0) {
            ps[(rw * 16 + gr) * 2 + ch]     = v0;
            ps[(rw * 16 + gr + 8) * 2 + ch] = v1;
        }
    }
    __syncthreads();
    if (tid < 128) {
        float iv = 1.0f / (ps[tid * 2] + ps[tid * 2 + 1]);
        inv[tid] = iv;
        pinv[(long)z * SEQ + brow + tid] = iv;
    }
    __syncthreads();

    // ---- O reduce across column halves via smem, normalize, store
    constexpr int OP = 66;                                        // padded pitch
    float* obuf = reinterpret_cast<float*>(smem + KOFF + 2048);   // [128][66]
    if (ch == 1) {
#pragma unroll
        for (int nt2 = 0; nt2 < 8; nt2++) {
            int col = nt2 * 8 + qc;
            int r0 = rw * 16 + gr;
            obuf[r0 * OP + col]           = o_acc[nt2][0];
            obuf[r0 * OP + col + 1]       = o_acc[nt2][1];
            obuf[(r0 + 8) * OP + col]     = o_acc[nt2][2];
            obuf[(r0 + 8) * OP + col + 1] = o_acc[nt2][3];
        }
    }
    __syncthreads();
    if (ch == 0) {
        int r0 = rw * 16 + gr;
        float inv0 = inv[r0];
        float inv1 = inv[r0 + 8];
        float* Og = O + ((long)b * SEQ + brow + rw * 16) * DM + h * HD;
#pragma unroll
        for (int nt2 = 0; nt2 < 8; nt2++) {
            int col = nt2 * 8 + qc;
            float a0 = (o_acc[nt2][0] + obuf[r0 * OP + col])       * inv0;
            float a1 = (o_acc[nt2][1] + obuf[r0 * OP + col + 1])   * inv0;
            float a2 = (o_acc[nt2][2] + obuf[(r0+8) * OP + col])   * inv1;
            float a3 = (o_acc[nt2][3] + obuf[(r0+8) * OP + col+1]) * inv1;
            *reinterpret_cast<float2*>(Og + (long)gr * DM + col)       = make_float2(a0, a1);
            *reinterpret_cast<float2*>(Og + (long)(gr + 8) * DM + col) = make_float2(a2, a3);
        }
    }
}

// ---------------------------------------------------------------------------
// NT GEMM via mma.sync bf16, 3-term split: C = A[M,K] @ B[N,K]^T
// MODE 0: plain store. MODE 3: transposed store per head -> vt[bh][d][s].
// BM=BN=128, BK=32. 256 threads.
// ---------------------------------------------------------------------------
template<int MODE>
__global__ void __launch_bounds__(256, 1) gemm_nt_mma(
    const float* __restrict__ A, const float* __restrict__ B, float* __restrict__ C,
    int K, int lda, int ldb, int ldc)
{
    constexpr int BM = 128, BN = 128, BK = 32;
    constexpr int ROWB = 80;
    constexpr int A_PLANE = BM * ROWB;
    constexpr int B_PLANE = BN * ROWB;
    constexpr int STAGE = 2 * A_PLANE + 2 * B_PLANE;

    extern __shared__ char smem[];
    const uint32_t sb = smem_u32(smem);

    const int tid = threadIdx.x, lane = tid & 31, wid = tid >> 5;
    const int wm = wid & 1, wn = wid >> 1;
    const int brow = blockIdx.y * BM;
    const int bcol = blockIdx.x * BN;

    float acc[4][4][4];
#pragma unroll
    for (int i = 0; i < 4; i++)
#pragma unroll
        for (int j = 0; j < 4; j++)
#pragma unroll
            for (int r = 0; r < 4; r++) acc[i][j][r] = 0.0f;

    float4 va[4], vb[4];
    const int nc = K / BK;

    const int g = lane >> 3;
    const int lrow = (lane & 7) + ((g & 1) << 3);
    const int lc16 = (g >> 1) << 4;

    // prologue: chunk 0 -> buffer 0
    {
#pragma unroll
        for (int i = 0; i < 4; i++) {
            int f = tid + i * 256, r = f >> 3, fi = f & 7;
            va[i] = *reinterpret_cast<const float4*>(A + (long)(brow + r) * lda + fi * 4);
            vb[i] = *reinterpret_cast<const float4*>(B + (long)(bcol + r) * ldb + fi * 4);
        }
        char* st = smem;
#pragma unroll
        for (int i = 0; i < 4; i++) {
            int f = tid + i * 256, r = f >> 3, fi = f & 7;
            uint32_t h0, l0, h1, l1;
            split2(va[i].x, va[i].y, h0, l0); split2(va[i].z, va[i].w, h1, l1);
            *reinterpret_cast<uint2*>(st + r * ROWB + fi * 8)           = make_uint2(h0, h1);
            *reinterpret_cast<uint2*>(st + A_PLANE + r * ROWB + fi * 8) = make_uint2(l0, l1);
            split2(vb[i].x, vb[i].y, h0, l0); split2(vb[i].z, vb[i].w, h1, l1);
            *reinterpret_cast<uint2*>(st + 2 * A_PLANE + r * ROWB + fi * 8)           = make_uint2(h0, h1);
            *reinterpret_cast<uint2*>(st + 2 * A_PLANE + B_PLANE + r * ROWB + fi * 8) = make_uint2(l0, l1);
        }
    }

    for (int c = 0; c < nc; ++c) {
        __syncthreads();
        const int buf = c & 1;

        if (c + 1 < nc) {
            const int k0 = (c + 1) * BK;
#pragma unroll
            for (int i = 0; i < 4; i++) {
                int f = tid + i * 256, r = f >> 3, fi = f & 7;
                va[i] = *reinterpret_cast<const float4*>(A + (long)(brow + r) * lda + k0 + fi * 4);
                vb[i] = *reinterpret_cast<const float4*>(B + (long)(bcol + r) * ldb + k0 + fi * 4);
            }
        }

        {
            const uint32_t aHi = sb + buf * STAGE;
            const uint32_t aLo = aHi + A_PLANE;
            const uint32_t bHi = aHi + 2 * A_PLANE;
            const uint32_t bLo = bHi + B_PLANE;
#pragma unroll
            for (int kg = 0; kg < 2; kg++) {
                const int kb = kg * 32 + lc16;
                uint32_t a_h[4][4], a_l[4][4];
#pragma unroll
                for (int mt = 0; mt < 4; mt++) {
                    int r0 = wm * 64 + mt * 16 + lrow;
                    ldm4(aHi + r0 * ROWB + kb, a_h[mt]);
                    ldm4(aLo + r0 * ROWB + kb, a_l[mt]);
                }
                uint32_t b_h[4][2], b_l[4][2];
#pragma unroll
                for (int np = 0; np < 2; np++) {
                    int n0 = wn * 32 + np * 16 + lrow;
                    uint32_t t[4];
                    ldm4(bHi + n0 * ROWB + kb, t);
                    b_h[2*np][0] = t[0]; b_h[2*np+1][0] = t[1];
                    b_h[2*np][1] = t[2]; b_h[2*np+1][1] = t[3];
                    ldm4(bLo + n0 * ROWB + kb, t);
                    b_l[2*np][0] = t[0]; b_l[2*np+1][0] = t[1];
                    b_l[2*np][1] = t[2]; b_l[2*np+1][1] = t[3];
                }
#pragma unroll
                for (int mt = 0; mt < 4; mt++)
#pragma unroll
                    for (int nt = 0; nt < 4; nt++) {
                        mma16816(acc[mt][nt], a_h[mt], b_h[nt]);
                        mma16816(acc[mt][nt], a_h[mt], b_l[nt]);
                        mma16816(acc[mt][nt], a_l[mt], b_h[nt]);
                    }
            }
        }

        if (c + 1 < nc) {
            char* st = smem + (buf ^ 1) * STAGE;
#pragma unroll
            for (int i = 0; i < 4; i++) {
                int f = tid + i * 256, r = f >> 3, fi = f & 7;
                uint32_t h0, l0, h1, l1;
                split2(va[i].x, va[i].y, h0, l0); split2(va[i].z, va[i].w, h1, l1);
                *reinterpret_cast<uint2*>(st + r * ROWB + fi * 8)           = make_uint2(h0, h1);
                *reinterpret_cast<uint2*>(st + A_PLANE + r * ROWB + fi * 8) = make_uint2(l0, l1);
                split2(vb[i].x, vb[i].y, h0, l0); split2(vb[i].z, vb[i].w, h1, l1);
                *reinterpret_cast<uint2*>(st + 2 * A_PLANE + r * ROWB + fi * 8)           = make_uint2(h0, h1);
                *reinterpret_cast<uint2*>(st + 2 * A_PLANE + B_PLANE + r * ROWB + fi * 8) = make_uint2(l0, l1);
            }
        }
    }

    if (MODE == 0) {
#pragma unroll
        for (int mt = 0; mt < 4; mt++)
#pragma unroll
            for (int nt = 0; nt < 4; nt++) {
                long row = brow + wm * 64 + mt * 16 + (lane >> 2);
                long col = bcol + wn * 32 + nt * 8 + (lane & 3) * 2;
                *reinterpret_cast<float2*>(C + row * ldc + col) =
                    make_float2(acc[mt][nt][0], acc[mt][nt][1]);
                *reinterpret_cast<float2*>(C + (row + 8) * ldc + col) =
                    make_float2(acc[mt][nt][2], acc[mt][nt][3]);
            }
    } else {
        // MODE 3: transpose via smem, write vt[bh][d][s] (C = vt base)
        constexpr int TP = 132;
        __syncthreads();
        float* tb = reinterpret_cast<float*>(smem);  // [128 d][132 s]
#pragma unroll
        for (int mt = 0; mt < 4; mt++)
#pragma unroll
            for (int nt = 0; nt < 4; nt++) {
                int s0 = wm * 64 + mt * 16 + (lane >> 2);
                int d0 = wn * 32 + nt * 8 + (lane & 3) * 2;
                tb[d0 * TP + s0]           = acc[mt][nt][0];
                tb[(d0 + 1) * TP + s0]     = acc[mt][nt][1];
                tb[d0 * TP + s0 + 8]       = acc[mt][nt][2];
                tb[(d0 + 1) * TP + s0 + 8] = acc[mt][nt][3];
            }
        __syncthreads();
        const int bb = brow >> 11;          // batch
        const int srow0 = brow & 2047;
        const int h0 = bcol >> 6;           // first of 2 heads in this col block
#pragma unroll
        for (int i = 0; i < 16; i++) {
            int f = tid + i * 256;
            int d = f >> 5, s = (f & 31) * 4;
            float4 v = *reinterpret_cast<float4*>(&tb[d * TP + s]);
            int hh = h0 + (d >> 6), dd = d & 63;
            *reinterpret_cast<float4*>(
                C + ((long)(bb * NH + hh) * HD + dd) * SEQ + srow0 + s) = v;
        }
    }
}

// ---------------------------------------------------------------------------
// attn[row][:] *= pinv[row]  (one block per row, 256 thr x 2 float4)
// ---------------------------------------------------------------------------
__global__ void __launch_bounds__(256) normalize_attn(
    float* __restrict__ attn, const float* __restrict__ pinv)
{
    long row = blockIdx.x;
    float inv = pinv[row];
    float4* p = reinterpret_cast<float4*>(attn + row * 2048);
    int t = threadIdx.x;
    float4 a = p[t];
    a.x *= inv; a.y *= inv; a.z *= inv; a.w *= inv;
    p[t] = a;
    float4 c = p[t + 256];
    c.x *= inv; c.y *= inv; c.z *= inv; c.w *= inv;
    p[t + 256] = c;
}

// ---------------------------------------------------------------------------
extern "C" void kernel_launch(void* const* d_in, const int* in_sizes, int n_in,
                              void* d_out, int out_size)
{
    const float* x  = (const float*)d_in[0];
    const float* Wq = (const float*)d_in[1];
    const float* Wk = (const float*)d_in[2];
    const float* Wv = (const float*)d_in[3];
    const float* Wo = (const float*)d_in[4];
    float* out = (float*)d_out;

    float *q, *k, *vt, *o, *pinv;
    cudaGetSymbolAddress((void**)&q,    g_q);
    cudaGetSymbolAddress((void**)&k,    g_k);
    cudaGetSymbolAddress((void**)&vt,   g_vt);
    cudaGetSymbolAddress((void**)&o,    g_o);
    cudaGetSymbolAddress((void**)&pinv, g_pinv);

    const long OUT_ELEMS = (long)MTOT * DM;      // 4194304
    float* attn = out + OUT_ELEMS;               // verified layout

    constexpr int SMEMG = 2 * (2 * 128 * 80 + 2 * 128 * 80);  // 81920
    constexpr int SMEMF = 110592 + 2 * 2 * 17408;             // 180224
    cudaFuncSetAttribute(gemm_nt_mma<0>, cudaFuncAttributeMaxDynamicSharedMemorySize, SMEMG);
    cudaFuncSetAttribute(gemm_nt_mma<3>, cudaFuncAttributeMaxDynamicSharedMemorySize, SMEMG);
    cudaFuncSetAttribute(attn_fused,     cudaFuncAttributeMaxDynamicSharedMemorySize, SMEMF);

    const float scale = 0.125f;  // 1/sqrt(64)
    dim3 thr(256);
    dim3 gproj(DM / 128, MTOT / 128, 1);

    // 0) V projection with transposed store -> vt
    gemm_nt_mma<3><<<gproj, thr, SMEMG>>>(x, Wv, vt, DM, DM, DM, DM);
    // 1-2) Q/K projections
    gemm_nt_mma<0><<<gproj, thr, SMEMG>>>(x, Wq, q, DM, DM, DM, DM);
    gemm_nt_mma<0><<<gproj, thr, SMEMG>>>(x, Wk, k, DM, DM, DM, DM);

    // 3) fused: expP (unnormalized) + pinv + O (normalized)  [profiled slot]
    dim3 gf(1, SEQ / 128, NB * NH);
    attn_fused<<<gf, dim3(512), SMEMF>>>(q, k, vt, attn, o, pinv, scale);

    // 4) normalize attn in-place
    normalize_attn<<<NB * NH * SEQ, 256>>>(attn, pinv);

    // 5) out = O @ Wo^T
    gemm_nt_mma<0><<<gproj, thr, SMEMG>>>(o, Wo, out, DM, DM, DM, DM);
}

// round 13
// speedup vs baseline: 1.0798x; 1.0298x over previous
#include <cuda_runtime.h>
#include <cuda_bf16.h>
#include <cstdint>

#define NB   2
#define SEQ  2048
#define DM   1024
#define NH   16
#define HD   64
#define MTOT (NB*SEQ)   // 4096

// Scratch (static device globals — allocation-free per harness rules)
__device__ float g_q[MTOT * DM];
__device__ __nv_bfloat16 g_khi[MTOT * DM];
__device__ __nv_bfloat16 g_klo[MTOT * DM];
__device__ __nv_bfloat16 g_vthi[NB * NH * HD * SEQ];  // V^T hi per (b,h): [HD][SEQ]
__device__ __nv_bfloat16 g_vtlo[NB * NH * HD * SEQ];
__device__ float g_o[MTOT * DM];
__device__ float g_pinv[(long)NB * NH * SEQ];  // per-row INVERSE exp sums

// ---------------------------------------------------------------------------
// helpers
// ---------------------------------------------------------------------------
__device__ __forceinline__ uint32_t smem_u32(const void* p) {
    uint32_t a;
    asm("{ .reg .u64 t; cvta.to.shared.u64 t, %1; cvt.u32.u64 %0, t; }"
        : "=r"(a) : "l"(p));
    return a;
}

// 3-term bf16 split: x = hi + lo (hi = bf16(x), lo = bf16(x - hi)).
__device__ __forceinline__ void split2(float x, float y, uint32_t& hi, uint32_t& lo) {
    __nv_bfloat16 hx = __float2bfloat16_rn(x);
    __nv_bfloat16 hy = __float2bfloat16_rn(y);
    float rx = x - __bfloat162float(hx);
    float ry = y - __bfloat162float(hy);
    __nv_bfloat16 lx = __float2bfloat16_rn(rx);
    __nv_bfloat16 ly = __float2bfloat16_rn(ry);
    hi = ((uint32_t)__bfloat16_as_ushort(hy) << 16) | (uint32_t)__bfloat16_as_ushort(hx);
    lo = ((uint32_t)__bfloat16_as_ushort(ly) << 16) | (uint32_t)__bfloat16_as_ushort(lx);
}

__device__ __forceinline__ void ldm4(uint32_t addr, uint32_t r[4]) {
    asm volatile("ldmatrix.sync.aligned.m8n8.x4.shared.b16 {%0,%1,%2,%3}, [%4];"
                 : "=r"(r[0]), "=r"(r[1]), "=r"(r[2]), "=r"(r[3]) : "r"(addr));
}

__device__ __forceinline__ void mma16816(float c[4], const uint32_t a[4], const uint32_t b[2]) {
    asm volatile(
        "mma.sync.aligned.m16n8k16.row.col.f32.bf16.bf16.f32 "
        "{%0,%1,%2,%3}, {%4,%5,%6,%7}, {%8,%9}, {%0,%1,%2,%3};"
        : "+f"(c[0]), "+f"(c[1]), "+f"(c[2]), "+f"(c[3])
        : "r"(a[0]), "r"(a[1]), "r"(a[2]), "r"(a[3]), "r"(b[0]), "r"(b[1]));
}

#define CP_ASYNC16(dst, src) \
    asm volatile("cp.async.cg.shared.global [%0], [%1], 16;" \
                 :: "r"(dst), "l"(src) : "memory")
#define CP_COMMIT() asm volatile("cp.async.commit_group;" ::: "memory")
#define CP_WAIT0()  asm volatile("cp.async.wait_group 0;" ::: "memory")

// ---------------------------------------------------------------------------
// Fused attention core, 512 threads = 16 warps. Per (b,h) and 128-row strip:
//   expP = exp(alpha * Q K^T) -> written unnormalized to P (attn region)
//   pinv[row] = 1 / full row sum -> gmem (for the normalize pass)
//   O = (expP @ V) * pinv      -> written to O
// K and V arrive PRE-SPLIT into bf16 hi/lo planes (produced by the projection
// epilogues), so staging is pure cp.async — no registers, no split math.
// Warp wid: row group (wid&7)*16, column half (wid>>3)*64 of each 128-col tile.
// ---------------------------------------------------------------------------
__global__ void __launch_bounds__(512, 1) attn_fused(
    const float* __restrict__ Q,
    const __nv_bfloat16* __restrict__ KHI, const __nv_bfloat16* __restrict__ KLO,
    const __nv_bfloat16* __restrict__ VHI, const __nv_bfloat16* __restrict__ VLO,
    float* __restrict__ P, float* __restrict__ O, float* __restrict__ pinv,
    float alpha)
{
    constexpr int PITCH  = 144;               // K rows: 128B bf16 + 16B pad
    constexpr int PLANE  = 128 * PITCH;       // 18432
    constexpr int VPITCH = 272;               // VT rows: 256B bf16 + 16B pad
    constexpr int VPLANE = 64 * VPITCH;       // 17408
    constexpr int KOFF   = 2 * PLANE;         // 36864 (Q hi/lo planes first)
    constexpr int VOFF   = KOFF + 4 * PLANE;  // 110592
    extern __shared__ char smem[];
    const uint32_t sb = smem_u32(smem);

    const int z = blockIdx.z;                  // b*NH + h
    const int b = z / NH, h = z % NH;
    const int brow = blockIdx.y * 128;
    const float* Aq = Q + (long)b * SEQ * DM + (long)h * HD;
    const __nv_bfloat16* Khi = KHI + (long)b * SEQ * DM + (long)h * HD;
    const __nv_bfloat16* Klo = KLO + (long)b * SEQ * DM + (long)h * HD;
    const __nv_bfloat16* Vhi = VHI + (long)z * HD * SEQ;
    const __nv_bfloat16* Vlo = VLO + (long)z * HD * SEQ;
    float* C = P + (long)z * SEQ * SEQ;

    const int tid = threadIdx.x, lane = tid & 31, wid = tid >> 5;
    const int rw = wid & 7;                    // row group (16 rows)
    const int ch = wid >> 3;                   // column half (64 cols)
    const int g = lane >> 3;
    const int lrow = (lane & 7) + ((g & 1) << 3);
    const int lc16 = (g >> 1) << 4;
    const int gr = lane >> 2, qc = (lane & 3) * 2;

    // stage K tile (2 planes x 128 rows x 8 16B-chunks) + V tile (2 x 64 x 16)
    auto stage_tiles = [&](int tile, int s) {
#pragma unroll
        for (int i = 0; i < 4; i++) {
            int f = tid + i * 512;
            int pl = f >> 10, r = (f >> 3) & 127, fi = f & 7;
            const __nv_bfloat16* src =
                (pl ? Klo : Khi) + (long)(tile * 128 + r) * DM + fi * 8;
            uint32_t dst = sb + KOFF + (uint32_t)s * 2 * PLANE + pl * PLANE
                         + r * PITCH + fi * 16;
            CP_ASYNC16(dst, src);
        }
#pragma unroll
        for (int i = 0; i < 4; i++) {
            int f = tid + i * 512;
            int pl = f >> 10, r = (f >> 4) & 63, fi = f & 15;
            const __nv_bfloat16* src =
                (pl ? Vlo : Vhi) + (long)r * SEQ + tile * 128 + fi * 8;
            uint32_t dst = sb + VOFF + (uint32_t)s * 2 * VPLANE + pl * VPLANE
                         + r * VPITCH + fi * 16;
            CP_ASYNC16(dst, src);
        }
    };

    // ---- prologue: async-stage K0/V0, then load + split Q strip (once)
    stage_tiles(0, 0);
    CP_COMMIT();
#pragma unroll
    for (int i = 0; i < 4; i++) {
        int f = tid + i * 512, r = f >> 4, fi = f & 15;
        float4 v = *reinterpret_cast<const float4*>(Aq + (long)(brow + r) * DM + fi * 4);
        uint32_t h0, l0, h1, l1;
        split2(v.x, v.y, h0, l0); split2(v.z, v.w, h1, l1);
        *reinterpret_cast<uint2*>(smem + r * PITCH + fi * 8)         = make_uint2(h0, h1);
        *reinterpret_cast<uint2*>(smem + PLANE + r * PITCH + fi * 8) = make_uint2(l0, l1);
    }
    CP_WAIT0();
    __syncthreads();

    float o_acc[8][4];
#pragma unroll
    for (int i = 0; i < 8; i++)
#pragma unroll
        for (int j = 0; j < 4; j++) o_acc[i][j] = 0.0f;
    float rs0 = 0.0f, rs1 = 0.0f;

    for (int ct = 0; ct < 16; ++ct) {
        const int buf = ct & 1;

        // async-stage next tile into the other buffers
        if (ct < 15) {
            stage_tiles(ct + 1, buf ^ 1);
            CP_COMMIT();
        }

        // ---- scores: acc(16x64) = Q_w(16x64) @ K_half(64x64)^T, 3-term split
        float acc[8][4];
#pragma unroll
        for (int i = 0; i < 8; i++)
#pragma unroll
            for (int j = 0; j < 4; j++) acc[i][j] = 0.0f;

        const uint32_t kHi = sb + KOFF + (uint32_t)buf * 2 * PLANE;
        const uint32_t kLo = kHi + PLANE;
#pragma unroll
        for (int kg = 0; kg < 4; kg++) {
            const int kb = kg * 32 + lc16;
            uint32_t a_h[4], a_l[4];
            int r0 = rw * 16 + lrow;
            ldm4(sb + r0 * PITCH + kb, a_h);
            ldm4(sb + PLANE + r0 * PITCH + kb, a_l);
#pragma unroll
            for (int np = 0; np < 4; np++) {
                int n0 = ch * 64 + np * 16 + lrow;
                uint32_t th[4], tl[4];
                ldm4(kHi + n0 * PITCH + kb, th);
                ldm4(kLo + n0 * PITCH + kb, tl);
                uint32_t bh0[2] = {th[0], th[2]}, bh1[2] = {th[1], th[3]};
                uint32_t bl0[2] = {tl[0], tl[2]}, bl1[2] = {tl[1], tl[3]};
                mma16816(acc[2*np],     a_h, bh0);
                mma16816(acc[2*np],     a_h, bl0);
                mma16816(acc[2*np],     a_l, bh0);
                mma16816(acc[2*np + 1], a_h, bh1);
                mma16816(acc[2*np + 1], a_h, bl1);
                mma16816(acc[2*np + 1], a_l, bh1);
            }
        }

        // ---- exp + P store + register A-frag conversion + PV MMA
        const uint32_t vHi = sb + VOFF + (uint32_t)buf * 2 * VPLANE;
        const uint32_t vLo = vHi + VPLANE;
        const long rowg = brow + rw * 16 + gr;
#pragma unroll
        for (int kk = 0; kk < 4; kk++) {
            float e00 = __expf(alpha * acc[2*kk][0]), e01 = __expf(alpha * acc[2*kk][1]);
            float e02 = __expf(alpha * acc[2*kk][2]), e03 = __expf(alpha * acc[2*kk][3]);
            float e10 = __expf(alpha * acc[2*kk+1][0]), e11 = __expf(alpha * acc[2*kk+1][1]);
            float e12 = __expf(alpha * acc[2*kk+1][2]), e13 = __expf(alpha * acc[2*kk+1][3]);
            rs0 += (e00 + e01) + (e10 + e11);
            rs1 += (e02 + e03) + (e12 + e13);
            long col = (long)ct * 128 + ch * 64 + kk * 16 + qc;
            *reinterpret_cast<float2*>(C + rowg * SEQ + col)           = make_float2(e00, e01);
            *reinterpret_cast<float2*>(C + (rowg + 8) * SEQ + col)     = make_float2(e02, e03);
            *reinterpret_cast<float2*>(C + rowg * SEQ + col + 8)       = make_float2(e10, e11);
            *reinterpret_cast<float2*>(C + (rowg + 8) * SEQ + col + 8) = make_float2(e12, e13);

            uint32_t pa_h[4], pa_l[4];
            split2(e00, e01, pa_h[0], pa_l[0]);
            split2(e02, e03, pa_h[1], pa_l[1]);
            split2(e10, e11, pa_h[2], pa_l[2]);
            split2(e12, e13, pa_h[3], pa_l[3]);

            const int vb = ch * 128 + kk * 32 + lc16;
#pragma unroll
            for (int np2 = 0; np2 < 4; np2++) {
                int n0 = np2 * 16 + lrow;
                uint32_t th[4], tl[4];
                ldm4(vHi + n0 * VPITCH + vb, th);
                ldm4(vLo + n0 * VPITCH + vb, tl);
                uint32_t bh0[2] = {th[0], th[2]}, bh1[2] = {th[1], th[3]};
                uint32_t bl0[2] = {tl[0], tl[2]}, bl1[2] = {tl[1], tl[3]};
                mma16816(o_acc[2*np2],     pa_h, bh0);
                mma16816(o_acc[2*np2],     pa_h, bl0);
                mma16816(o_acc[2*np2],     pa_l, bh0);
                mma16816(o_acc[2*np2 + 1], pa_h, bh1);
                mma16816(o_acc[2*np2 + 1], pa_h, bl1);
                mma16816(o_acc[2*np2 + 1], pa_l, bh1);
            }
        }

        if (ct < 15) CP_WAIT0();
        __syncthreads();
    }

    // ---- row sums: combine halves (deterministic), invert, write pinv
    float* ps  = reinterpret_cast<float*>(smem + KOFF);          // [128][2]
    float* inv = reinterpret_cast<float*>(smem + KOFF + 1024);   // [128]
    {
        float v0 = rs0;
        v0 += __shfl_xor_sync(0xffffffffu, v0, 1);
        v0 += __shfl_xor_sync(0xffffffffu, v0, 2);
        float v1 = rs1;
        v1 += __shfl_xor_sync(0xffffffffu, v1, 1);
        v1 += __shfl_xor_sync(0xffffffffu, v1, 2);
        if ((lane & 3) == 0) {
            ps[(rw * 16 + gr) * 2 + ch]     = v0;
            ps[(rw * 16 + gr + 8) * 2 + ch] = v1;
        }
    }
    __syncthreads();
    if (tid < 128) {
        float iv = 1.0f / (ps[tid * 2] + ps[tid * 2 + 1]);
        inv[tid] = iv;
        pinv[(long)z * SEQ + brow + tid] = iv;
    }
    __syncthreads();

    // ---- O reduce across column halves via smem, normalize, store
    constexpr int OP = 66;                                        // padded pitch
    float* obuf = reinterpret_cast<float*>(smem + KOFF + 2048);   // [128][66]
    if (ch == 1) {
#pragma unroll
        for (int nt2 = 0; nt2 < 8; nt2++) {
            int col = nt2 * 8 + qc;
            int r0 = rw * 16 + gr;
            obuf[r0 * OP + col]           = o_acc[nt2][0];
            obuf[r0 * OP + col + 1]       = o_acc[nt2][1];
            obuf[(r0 + 8) * OP + col]     = o_acc[nt2][2];
            obuf[(r0 + 8) * OP + col + 1] = o_acc[nt2][3];
        }
    }
    __syncthreads();
    if (ch == 0) {
        int r0 = rw * 16 + gr;
        float inv0 = inv[r0];
        float inv1 = inv[r0 + 8];
        float* Og = O + ((long)b * SEQ + brow + rw * 16) * DM + h * HD;
#pragma unroll
        for (int nt2 = 0; nt2 < 8; nt2++) {
            int col = nt2 * 8 + qc;
            float a0 = (o_acc[nt2][0] + obuf[r0 * OP + col])       * inv0;
            float a1 = (o_acc[nt2][1] + obuf[r0 * OP + col + 1])   * inv0;
            float a2 = (o_acc[nt2][2] + obuf[(r0+8) * OP + col])   * inv1;
            float a3 = (o_acc[nt2][3] + obuf[(r0+8) * OP + col+1]) * inv1;
            *reinterpret_cast<float2*>(Og + (long)gr * DM + col)       = make_float2(a0, a1);
            *reinterpret_cast<float2*>(Og + (long)(gr + 8) * DM + col) = make_float2(a2, a3);
        }
    }
}

// ---------------------------------------------------------------------------
// NT GEMM via mma.sync bf16, 3-term split: C = A[M,K] @ B[N,K]^T
// MODE 0: plain fp32 store (C).
// MODE 1: bf16 hi/lo plane store (C=hi, C2=lo), same layout as MODE 0.
// MODE 3: transposed per-head bf16 hi/lo store -> vt[bh][d][s] (C=hi, C2=lo).
// BM=BN=128, BK=32. 256 threads.
// ---------------------------------------------------------------------------
template<int MODE>
__global__ void __launch_bounds__(256, 1) gemm_nt_mma(
    const float* __restrict__ A, const float* __restrict__ B,
    float* __restrict__ C, float* __restrict__ C2,
    int K, int lda, int ldb, int ldc)
{
    constexpr int BM = 128, BN = 128, BK = 32;
    constexpr int ROWB = 80;
    constexpr int A_PLANE = BM * ROWB;
    constexpr int B_PLANE = BN * ROWB;
    constexpr int STAGE = 2 * A_PLANE + 2 * B_PLANE;

    extern __shared__ char smem[];
    const uint32_t sb = smem_u32(smem);

    const int tid = threadIdx.x, lane = tid & 31, wid = tid >> 5;
    const int wm = wid & 1, wn = wid >> 1;
    const int brow = blockIdx.y * BM;
    const int bcol = blockIdx.x * BN;

    float acc[4][4][4];
#pragma unroll
    for (int i = 0; i < 4; i++)
#pragma unroll
        for (int j = 0; j < 4; j++)
#pragma unroll
            for (int r = 0; r < 4; r++) acc[i][j][r] = 0.0f;

    float4 va[4], vb[4];
    const int nc = K / BK;

    const int g = lane >> 3;
    const int lrow = (lane & 7) + ((g & 1) << 3);
    const int lc16 = (g >> 1) << 4;

    // prologue: chunk 0 -> buffer 0
    {
#pragma unroll
        for (int i = 0; i < 4; i++) {
            int f = tid + i * 256, r = f >> 3, fi = f & 7;
            va[i] = *reinterpret_cast<const float4*>(A + (long)(brow + r) * lda + fi * 4);
            vb[i] = *reinterpret_cast<const float4*>(B + (long)(bcol + r) * ldb + fi * 4);
        }
        char* st = smem;
#pragma unroll
        for (int i = 0; i < 4; i++) {
            int f = tid + i * 256, r = f >> 3, fi = f & 7;
            uint32_t h0, l0, h1, l1;
            split2(va[i].x, va[i].y, h0, l0); split2(va[i].z, va[i].w, h1, l1);
            *reinterpret_cast<uint2*>(st + r * ROWB + fi * 8)           = make_uint2(h0, h1);
            *reinterpret_cast<uint2*>(st + A_PLANE + r * ROWB + fi * 8) = make_uint2(l0, l1);
            split2(vb[i].x, vb[i].y, h0, l0); split2(vb[i].z, vb[i].w, h1, l1);
            *reinterpret_cast<uint2*>(st + 2 * A_PLANE + r * ROWB + fi * 8)           = make_uint2(h0, h1);
            *reinterpret_cast<uint2*>(st + 2 * A_PLANE + B_PLANE + r * ROWB + fi * 8) = make_uint2(l0, l1);
        }
    }

    for (int c = 0; c < nc; ++c) {
        __syncthreads();
        const int buf = c & 1;

        if (c + 1 < nc) {
            const int k0 = (c + 1) * BK;
#pragma unroll
            for (int i = 0; i < 4; i++) {
                int f = tid + i * 256, r = f >> 3, fi = f & 7;
                va[i] = *reinterpret_cast<const float4*>(A + (long)(brow + r) * lda + k0 + fi * 4);
                vb[i] = *reinterpret_cast<const float4*>(B + (long)(bcol + r) * ldb + k0 + fi * 4);
            }
        }

        {
            const uint32_t aHi = sb + buf * STAGE;
            const uint32_t aLo = aHi + A_PLANE;
            const uint32_t bHi = aHi + 2 * A_PLANE;
            const uint32_t bLo = bHi + B_PLANE;
#pragma unroll
            for (int kg = 0; kg < 2; kg++) {
                const int kb = kg * 32 + lc16;
                uint32_t a_h[4][4], a_l[4][4];
#pragma unroll
                for (int mt = 0; mt < 4; mt++) {
                    int r0 = wm * 64 + mt * 16 + lrow;
                    ldm4(aHi + r0 * ROWB + kb, a_h[mt]);
                    ldm4(aLo + r0 * ROWB + kb, a_l[mt]);
                }
                uint32_t b_h[4][2], b_l[4][2];
#pragma unroll
                for (int np = 0; np < 2; np++) {
                    int n0 = wn * 32 + np * 16 + lrow;
                    uint32_t t[4];
                    ldm4(bHi + n0 * ROWB + kb, t);
                    b_h[2*np][0] = t[0]; b_h[2*np+1][0] = t[1];
                    b_h[2*np][1] = t[2]; b_h[2*np+1][1] = t[3];
                    ldm4(bLo + n0 * ROWB + kb, t);
                    b_l[2*np][0] = t[0]; b_l[2*np+1][0] = t[1];
                    b_l[2*np][1] = t[2]; b_l[2*np+1][1] = t[3];
                }
#pragma unroll
                for (int mt = 0; mt < 4; mt++)
#pragma unroll
                    for (int nt = 0; nt < 4; nt++) {
                        mma16816(acc[mt][nt], a_h[mt], b_h[nt]);
                        mma16816(acc[mt][nt], a_h[mt], b_l[nt]);
                        mma16816(acc[mt][nt], a_l[mt], b_h[nt]);
                    }
            }
        }

        if (c + 1 < nc) {
            char* st = smem + (buf ^ 1) * STAGE;
#pragma unroll
            for (int i = 0; i < 4; i++) {
                int f = tid + i * 256, r = f >> 3, fi = f & 7;
                uint32_t h0, l0, h1, l1;
                split2(va[i].x, va[i].y, h0, l0); split2(va[i].z, va[i].w, h1, l1);
                *reinterpret_cast<uint2*>(st + r * ROWB + fi * 8)           = make_uint2(h0, h1);
                *reinterpret_cast<uint2*>(st + A_PLANE + r * ROWB + fi * 8) = make_uint2(l0, l1);
                split2(vb[i].x, vb[i].y, h0, l0); split2(vb[i].z, vb[i].w, h1, l1);
                *reinterpret_cast<uint2*>(st + 2 * A_PLANE + r * ROWB + fi * 8)           = make_uint2(h0, h1);
                *reinterpret_cast<uint2*>(st + 2 * A_PLANE + B_PLANE + r * ROWB + fi * 8) = make_uint2(l0, l1);
            }
        }
    }

    if (MODE == 0) {
#pragma unroll
        for (int mt = 0; mt < 4; mt++)
#pragma unroll
            for (int nt = 0; nt < 4; nt++) {
                long row = brow + wm * 64 + mt * 16 + (lane >> 2);
                long col = bcol + wn * 32 + nt * 8 + (lane & 3) * 2;
                *reinterpret_cast<float2*>(C + row * ldc + col) =
                    make_float2(acc[mt][nt][0], acc[mt][nt][1]);
                *reinterpret_cast<float2*>(C + (row + 8) * ldc + col) =
                    make_float2(acc[mt][nt][2], acc[mt][nt][3]);
            }
    } else if (MODE == 1) {
        __nv_bfloat16* hiP = reinterpret_cast<__nv_bfloat16*>(C);
        __nv_bfloat16* loP = reinterpret_cast<__nv_bfloat16*>(C2);
#pragma unroll
        for (int mt = 0; mt < 4; mt++)
#pragma unroll
            for (int nt = 0; nt < 4; nt++) {
                long row = brow + wm * 64 + mt * 16 + (lane >> 2);
                long col = bcol + wn * 32 + nt * 8 + (lane & 3) * 2;
                uint32_t h0, l0, h1, l1;
                split2(acc[mt][nt][0], acc[mt][nt][1], h0, l0);
                split2(acc[mt][nt][2], acc[mt][nt][3], h1, l1);
                *reinterpret_cast<uint32_t*>(hiP + row * ldc + col)       = h0;
                *reinterpret_cast<uint32_t*>(loP + row * ldc + col)       = l0;
                *reinterpret_cast<uint32_t*>(hiP + (row + 8) * ldc + col) = h1;
                *reinterpret_cast<uint32_t*>(loP + (row + 8) * ldc + col) = l1;
            }
    } else {
        // MODE 3: transpose via smem (fp32), then split + write bf16 planes
        constexpr int TP = 132;
        __syncthreads();
        float* tb = reinterpret_cast<float*>(smem);  // [128 d][132 s]
#pragma unroll
        for (int mt = 0; mt < 4; mt++)
#pragma unroll
            for (int nt = 0; nt < 4; nt++) {
                int s0 = wm * 64 + mt * 16 + (lane >> 2);
                int d0 = wn * 32 + nt * 8 + (lane & 3) * 2;
                tb[d0 * TP + s0]           = acc[mt][nt][0];
                tb[(d0 + 1) * TP + s0]     = acc[mt][nt][1];
                tb[d0 * TP + s0 + 8]       = acc[mt][nt][2];
                tb[(d0 + 1) * TP + s0 + 8] = acc[mt][nt][3];
            }
        __syncthreads();
        __nv_bfloat16* hiP = reinterpret_cast<__nv_bfloat16*>(C);
        __nv_bfloat16* loP = reinterpret_cast<__nv_bfloat16*>(C2);
        const int bb = brow >> 11;          // batch
        const int srow0 = brow & 2047;
        const int h0i = bcol >> 6;          // first of 2 heads in this col block
#pragma unroll
        for (int i = 0; i < 16; i++) {
            int f = tid + i * 256;
            int d = f >> 5, s = (f & 31) * 4;
            float4 v = *reinterpret_cast<float4*>(&tb[d * TP + s]);
            int hh = h0i + (d >> 6), dd = d & 63;
            long off = ((long)(bb * NH + hh) * HD + dd) * SEQ + srow0 + s;
            uint32_t h0, l0, h1, l1;
            split2(v.x, v.y, h0, l0); split2(v.z, v.w, h1, l1);
            *reinterpret_cast<uint2*>(hiP + off) = make_uint2(h0, h1);
            *reinterpret_cast<uint2*>(loP + off) = make_uint2(l0, l1);
        }
    }
}

// ---------------------------------------------------------------------------
// attn[row][:] *= pinv[row]  (one block per row, 256 thr x 2 float4)
// ---------------------------------------------------------------------------
__global__ void __launch_bounds__(256) normalize_attn(
    float* __restrict__ attn, const float* __restrict__ pinv)
{
    long row = blockIdx.x;
    float inv = pinv[row];
    float4* p = reinterpret_cast<float4*>(attn + row * 2048);
    int t = threadIdx.x;
    float4 a = p[t];
    a.x *= inv; a.y *= inv; a.z *= inv; a.w *= inv;
    p[t] = a;
    float4 c = p[t + 256];
    c.x *= inv; c.y *= inv; c.z *= inv; c.w *= inv;
    p[t + 256] = c;
}

// ---------------------------------------------------------------------------
extern "C" void kernel_launch(void* const* d_in, const int* in_sizes, int n_in,
                              void* d_out, int out_size)
{
    const float* x  = (const float*)d_in[0];
    const float* Wq = (const float*)d_in[1];
    const float* Wk = (const float*)d_in[2];
    const float* Wv = (const float*)d_in[3];
    const float* Wo = (const float*)d_in[4];
    float* out = (float*)d_out;

    float *q, *o, *pinv;
    __nv_bfloat16 *khi, *klo, *vthi, *vtlo;
    cudaGetSymbolAddress((void**)&q,    g_q);
    cudaGetSymbolAddress((void**)&khi,  g_khi);
    cudaGetSymbolAddress((void**)&klo,  g_klo);
    cudaGetSymbolAddress((void**)&vthi, g_vthi);
    cudaGetSymbolAddress((void**)&vtlo, g_vtlo);
    cudaGetSymbolAddress((void**)&o,    g_o);
    cudaGetSymbolAddress((void**)&pinv, g_pinv);

    const long OUT_ELEMS = (long)MTOT * DM;      // 4194304
    float* attn = out + OUT_ELEMS;               // verified layout

    constexpr int SMEMG = 2 * (2 * 128 * 80 + 2 * 128 * 80);  // 81920
    constexpr int SMEMF = 110592 + 2 * 2 * 17408;             // 180224
    cudaFuncSetAttribute(gemm_nt_mma<0>, cudaFuncAttributeMaxDynamicSharedMemorySize, SMEMG);
    cudaFuncSetAttribute(gemm_nt_mma<1>, cudaFuncAttributeMaxDynamicSharedMemorySize, SMEMG);
    cudaFuncSetAttribute(gemm_nt_mma<3>, cudaFuncAttributeMaxDynamicSharedMemorySize, SMEMG);
    cudaFuncSetAttribute(attn_fused,     cudaFuncAttributeMaxDynamicSharedMemorySize, SMEMF);

    const float scale = 0.125f;  // 1/sqrt(64)
    dim3 thr(256);
    dim3 gproj(DM / 128, MTOT / 128, 1);

    // 0) V projection -> transposed bf16 hi/lo planes
    gemm_nt_mma<3><<<gproj, thr, SMEMG>>>(x, Wv, (float*)vthi, (float*)vtlo, DM, DM, DM, DM);
    // 1) K projection -> bf16 hi/lo planes
    gemm_nt_mma<1><<<gproj, thr, SMEMG>>>(x, Wk, (float*)khi, (float*)klo, DM, DM, DM, DM);
    // 2) Q projection -> fp32
    gemm_nt_mma<0><<<gproj, thr, SMEMG>>>(x, Wq, q, nullptr, DM, DM, DM, DM);

    // 3) fused: expP (unnormalized) + pinv + O (normalized)  [profiled slot]
    dim3 gf(1, SEQ / 128, NB * NH);
    attn_fused<<<gf, dim3(512), SMEMF>>>(q, khi, klo, vthi, vtlo, attn, o, pinv, scale);

    // 4) normalize attn in-place
    normalize_attn<<<NB * NH * SEQ, 256>>>(attn, pinv);

    // 5) out = O @ Wo^T
    gemm_nt_mma<0><<<gproj, thr, SMEMG>>>(o, Wo, out, nullptr, DM, DM, DM, DM);
}

// round 15
// speedup vs baseline: 1.0799x; 1.0001x over previous
#include <cuda_runtime.h>
#include <cuda_bf16.h>
#include <cstdint>

#define NB   2
#define SEQ  2048
#define DM   1024
#define NH   16
#define HD   64
#define MTOT (NB*SEQ)   // 4096

// Scratch (static device globals — allocation-free per harness rules)
__device__ float g_q[MTOT * DM];
__device__ __nv_bfloat16 g_khi[MTOT * DM];
__device__ __nv_bfloat16 g_klo[MTOT * DM];
__device__ __nv_bfloat16 g_vthi[NB * NH * HD * SEQ];  // V^T hi per (b,h): [HD][SEQ]
__device__ __nv_bfloat16 g_vtlo[NB * NH * HD * SEQ];
__device__ float g_o[MTOT * DM];
__device__ float g_pinv[(long)NB * NH * SEQ];  // per-row INVERSE exp sums

// ---------------------------------------------------------------------------
// helpers
// ---------------------------------------------------------------------------
__device__ __forceinline__ uint32_t smem_u32(const void* p) {
    uint32_t a;
    asm("{ .reg .u64 t; cvta.to.shared.u64 t, %1; cvt.u32.u64 %0, t; }"
        : "=r"(a) : "l"(p));
    return a;
}

// 3-term bf16 split: x = hi + lo (hi = bf16(x), lo = bf16(x - hi)).
__device__ __forceinline__ void split2(float x, float y, uint32_t& hi, uint32_t& lo) {
    __nv_bfloat16 hx = __float2bfloat16_rn(x);
    __nv_bfloat16 hy = __float2bfloat16_rn(y);
    float rx = x - __bfloat162float(hx);
    float ry = y - __bfloat162float(hy);
    __nv_bfloat16 lx = __float2bfloat16_rn(rx);
    __nv_bfloat16 ly = __float2bfloat16_rn(ry);
    hi = ((uint32_t)__bfloat16_as_ushort(hy) << 16) | (uint32_t)__bfloat16_as_ushort(hx);
    lo = ((uint32_t)__bfloat16_as_ushort(ly) << 16) | (uint32_t)__bfloat16_as_ushort(lx);
}

__device__ __forceinline__ void ldm4(uint32_t addr, uint32_t r[4]) {
    asm volatile("ldmatrix.sync.aligned.m8n8.x4.shared.b16 {%0,%1,%2,%3}, [%4];"
                 : "=r"(r[0]), "=r"(r[1]), "=r"(r[2]), "=r"(r[3]) : "r"(addr));
}

__device__ __forceinline__ void mma16816(float c[4], const uint32_t a[4], const uint32_t b[2]) {
    asm volatile(
        "mma.sync.aligned.m16n8k16.row.col.f32.bf16.bf16.f32 "
        "{%0,%1,%2,%3}, {%4,%5,%6,%7}, {%8,%9}, {%0,%1,%2,%3};"
        : "+f"(c[0]), "+f"(c[1]), "+f"(c[2]), "+f"(c[3])
        : "r"(a[0]), "r"(a[1]), "r"(a[2]), "r"(a[3]), "r"(b[0]), "r"(b[1]));
}

#define CP_ASYNC16(dst, src) \
    asm volatile("cp.async.cg.shared.global [%0], [%1], 16;" \
                 :: "r"(dst), "l"(src) : "memory")
#define CP_COMMIT() asm volatile("cp.async.commit_group;" ::: "memory")
#define CP_WAIT0()  asm volatile("cp.async.wait_group 0;" ::: "memory")

// ---------------------------------------------------------------------------
// Fused attention core, 512 threads = 16 warps. Per (b,h) and 128-row strip:
//   expP = exp(alpha * Q K^T) -> written unnormalized to P (attn region)
//   pinv[row] = 1 / full row sum -> gmem (for the normalize pass)
//   O = (expP @ V) * pinv      -> written to O
// K and V arrive PRE-SPLIT into bf16 hi/lo planes (produced by the projection
// epilogues), so staging is pure cp.async — no registers, no split math.
// Warp wid: row group (wid&7)*16, column half (wid>>3)*64 of each 128-col tile.
// ---------------------------------------------------------------------------
__global__ void __launch_bounds__(512, 1) attn_fused(
    const float* __restrict__ Q,
    const __nv_bfloat16* __restrict__ KHI, const __nv_bfloat16* __restrict__ KLO,
    const __nv_bfloat16* __restrict__ VHI, const __nv_bfloat16* __restrict__ VLO,
    float* __restrict__ P, float* __restrict__ O, float* __restrict__ pinv,
    float alpha)
{
    constexpr int PITCH  = 144;               // K rows: 128B bf16 + 16B pad
    constexpr int PLANE  = 128 * PITCH;       // 18432
    constexpr int VPITCH = 272;               // VT rows: 256B bf16 + 16B pad
    constexpr int VPLANE = 64 * VPITCH;       // 17408
    constexpr int KOFF   = 2 * PLANE;         // 36864 (Q hi/lo planes first)
    constexpr int VOFF   = KOFF + 4 * PLANE;  // 110592
    extern __shared__ char smem[];
    const uint32_t sb = smem_u32(smem);

    const int z = blockIdx.z;                  // b*NH + h
    const int b = z / NH, h = z % NH;
    const int brow = blockIdx.y * 128;
    const float* Aq = Q + (long)b * SEQ * DM + (long)h * HD;
    const __nv_bfloat16* Khi = KHI + (long)b * SEQ * DM + (long)h * HD;
    const __nv_bfloat16* Klo = KLO + (long)b * SEQ * DM + (long)h * HD;
    const __nv_bfloat16* Vhi = VHI + (long)z * HD * SEQ;
    const __nv_bfloat16* Vlo = VLO + (long)z * HD * SEQ;
    float* C = P + (long)z * SEQ * SEQ;

    const int tid = threadIdx.x, lane = tid & 31, wid = tid >> 5;
    const int rw = wid & 7;                    // row group (16 rows)
    const int ch = wid >> 3;                   // column half (64 cols)
    const int g = lane >> 3;
    const int lrow = (lane & 7) + ((g & 1) << 3);
    const int lc16 = (g >> 1) << 4;
    const int gr = lane >> 2, qc = (lane & 3) * 2;

    // stage K tile (2 planes x 128 rows x 8 16B-chunks) + V tile (2 x 64 x 16)
    auto stage_tiles = [&](int tile, int s) {
#pragma unroll
        for (int i = 0; i < 4; i++) {
            int f = tid + i * 512;
            int pl = f >> 10, r = (f >> 3) & 127, fi = f & 7;
            const __nv_bfloat16* src =
                (pl ? Klo : Khi) + (long)(tile * 128 + r) * DM + fi * 8;
            uint32_t dst = sb + KOFF + (uint32_t)s * 2 * PLANE + pl * PLANE
                         + r * PITCH + fi * 16;
            CP_ASYNC16(dst, src);
        }
#pragma unroll
        for (int i = 0; i < 4; i++) {
            int f = tid + i * 512;
            int pl = f >> 10, r = (f >> 4) & 63, fi = f & 15;
            const __nv_bfloat16* src =
                (pl ? Vlo : Vhi) + (long)r * SEQ + tile * 128 + fi * 8;
            uint32_t dst = sb + VOFF + (uint32_t)s * 2 * VPLANE + pl * VPLANE
                         + r * VPITCH + fi * 16;
            CP_ASYNC16(dst, src);
        }
    };

    // ---- prologue: async-stage K0/V0, then load + split Q strip (once)
    stage_tiles(0, 0);
    CP_COMMIT();
#pragma unroll
    for (int i = 0; i < 4; i++) {
        int f = tid + i * 512, r = f >> 4, fi = f & 15;
        float4 v = *reinterpret_cast<const float4*>(Aq + (long)(brow + r) * DM + fi * 4);
        uint32_t h0, l0, h1, l1;
        split2(v.x, v.y, h0, l0); split2(v.z, v.w, h1, l1);
        *reinterpret_cast<uint2*>(smem + r * PITCH + fi * 8)         = make_uint2(h0, h1);
        *reinterpret_cast<uint2*>(smem + PLANE + r * PITCH + fi * 8) = make_uint2(l0, l1);
    }
    CP_WAIT0();
    __syncthreads();

    float o_acc[8][4];
#pragma unroll
    for (int i = 0; i < 8; i++)
#pragma unroll
        for (int j = 0; j < 4; j++) o_acc[i][j] = 0.0f;
    float rs0 = 0.0f, rs1 = 0.0f;

    for (int ct = 0; ct < 16; ++ct) {
        const int buf = ct & 1;

        // async-stage next tile into the other buffers
        if (ct < 15) {
            stage_tiles(ct + 1, buf ^ 1);
            CP_COMMIT();
        }

        // ---- scores: acc(16x64) = Q_w(16x64) @ K_half(64x64)^T, 3-term split
        float acc[8][4];
#pragma unroll
        for (int i = 0; i < 8; i++)
#pragma unroll
            for (int j = 0; j < 4; j++) acc[i][j] = 0.0f;

        const uint32_t kHi = sb + KOFF + (uint32_t)buf * 2 * PLANE;
        const uint32_t kLo = kHi + PLANE;
#pragma unroll
        for (int kg = 0; kg < 4; kg++) {
            const int kb = kg * 32 + lc16;
            uint32_t a_h[4], a_l[4];
            int r0 = rw * 16 + lrow;
            ldm4(sb + r0 * PITCH + kb, a_h);
            ldm4(sb + PLANE + r0 * PITCH + kb, a_l);
#pragma unroll
            for (int np = 0; np < 4; np++) {
                int n0 = ch * 64 + np * 16 + lrow;
                uint32_t th[4], tl[4];
                ldm4(kHi + n0 * PITCH + kb, th);
                ldm4(kLo + n0 * PITCH + kb, tl);
                uint32_t bh0[2] = {th[0], th[2]}, bh1[2] = {th[1], th[3]};
                uint32_t bl0[2] = {tl[0], tl[2]}, bl1[2] = {tl[1], tl[3]};
                mma16816(acc[2*np],     a_h, bh0);
                mma16816(acc[2*np],     a_h, bl0);
                mma16816(acc[2*np],     a_l, bh0);
                mma16816(acc[2*np + 1], a_h, bh1);
                mma16816(acc[2*np + 1], a_h, bl1);
                mma16816(acc[2*np + 1], a_l, bh1);
            }
        }

        // ---- exp + P store + register A-frag conversion + PV MMA
        const uint32_t vHi = sb + VOFF + (uint32_t)buf * 2 * VPLANE;
        const uint32_t vLo = vHi + VPLANE;
        const long rowg = brow + rw * 16 + gr;
#pragma unroll
        for (int kk = 0; kk < 4; kk++) {
            float e00 = __expf(alpha * acc[2*kk][0]), e01 = __expf(alpha * acc[2*kk][1]);
            float e02 = __expf(alpha * acc[2*kk][2]), e03 = __expf(alpha * acc[2*kk][3]);
            float e10 = __expf(alpha * acc[2*kk+1][0]), e11 = __expf(alpha * acc[2*kk+1][1]);
            float e12 = __expf(alpha * acc[2*kk+1][2]), e13 = __expf(alpha * acc[2*kk+1][3]);
            rs0 += (e00 + e01) + (e10 + e11);
            rs1 += (e02 + e03) + (e12 + e13);
            long col = (long)ct * 128 + ch * 64 + kk * 16 + qc;
            *reinterpret_cast<float2*>(C + rowg * SEQ + col)           = make_float2(e00, e01);
            *reinterpret_cast<float2*>(C + (rowg + 8) * SEQ + col)     = make_float2(e02, e03);
            *reinterpret_cast<float2*>(C + rowg * SEQ + col + 8)       = make_float2(e10, e11);
            *reinterpret_cast<float2*>(C + (rowg + 8) * SEQ + col + 8) = make_float2(e12, e13);

            uint32_t pa_h[4], pa_l[4];
            split2(e00, e01, pa_h[0], pa_l[0]);
            split2(e02, e03, pa_h[1], pa_l[1]);
            split2(e10, e11, pa_h[2], pa_l[2]);
            split2(e12, e13, pa_h[3], pa_l[3]);

            const int vb = ch * 128 + kk * 32 + lc16;
#pragma unroll
            for (int np2 = 0; np2 < 4; np2++) {
                int n0 = np2 * 16 + lrow;
                uint32_t th[4], tl[4];
                ldm4(vHi + n0 * VPITCH + vb, th);
                ldm4(vLo + n0 * VPITCH + vb, tl);
                uint32_t bh0[2] = {th[0], th[2]}, bh1[2] = {th[1], th[3]};
                uint32_t bl0[2] = {tl[0], tl[2]}, bl1[2] = {tl[1], tl[3]};
                mma16816(o_acc[2*np2],     pa_h, bh0);
                mma16816(o_acc[2*np2],     pa_h, bl0);
                mma16816(o_acc[2*np2],     pa_l, bh0);
                mma16816(o_acc[2*np2 + 1], pa_h, bh1);
                mma16816(o_acc[2*np2 + 1], pa_h, bl1);
                mma16816(o_acc[2*np2 + 1], pa_l, bh1);
            }
        }

        if (ct < 15) CP_WAIT0();
        __syncthreads();
    }

    // ---- row sums: combine halves (deterministic), invert, write pinv
    float* ps  = reinterpret_cast<float*>(smem + KOFF);          // [128][2]
    float* inv = reinterpret_cast<float*>(smem + KOFF + 1024);   // [128]
    {
        float v0 = rs0;
        v0 += __shfl_xor_sync(0xffffffffu, v0, 1);
        v0 += __shfl_xor_sync(0xffffffffu, v0, 2);
        float v1 = rs1;
        v1 += __shfl_xor_sync(0xffffffffu, v1, 1);
        v1 += __shfl_xor_sync(0xffffffffu, v1, 2);
        if ((lane & 3) == 0) {
            ps[(rw * 16 + gr) * 2 + ch]     = v0;
            ps[(rw * 16 + gr + 8) * 2 + ch] = v1;
        }
    }
    __syncthreads();
    if (tid < 128) {
        float iv = 1.0f / (ps[tid * 2] + ps[tid * 2 + 1]);
        inv[tid] = iv;
        pinv[(long)z * SEQ + brow + tid] = iv;
    }
    __syncthreads();

    // ---- O reduce across column halves via smem, normalize, store
    constexpr int OP = 66;                                        // padded pitch
    float* obuf = reinterpret_cast<float*>(smem + KOFF + 2048);   // [128][66]
    if (ch == 1) {
#pragma unroll
        for (int nt2 = 0; nt2 < 8; nt2++) {
            int col = nt2 * 8 + qc;
            int r0 = rw * 16 + gr;
            obuf[r0 * OP + col]           = o_acc[nt2][0];
            obuf[r0 * OP + col + 1]       = o_acc[nt2][1];
            obuf[(r0 + 8) * OP + col]     = o_acc[nt2][2];
            obuf[(r0 + 8) * OP + col + 1] = o_acc[nt2][3];
        }
    }
    __syncthreads();
    if (ch == 0) {
        int r0 = rw * 16 + gr;
        float inv0 = inv[r0];
        float inv1 = inv[r0 + 8];
        float* Og = O + ((long)b * SEQ + brow + rw * 16) * DM + h * HD;
#pragma unroll
        for (int nt2 = 0; nt2 < 8; nt2++) {
            int col = nt2 * 8 + qc;
            float a0 = (o_acc[nt2][0] + obuf[r0 * OP + col])       * inv0;
            float a1 = (o_acc[nt2][1] + obuf[r0 * OP + col + 1])   * inv0;
            float a2 = (o_acc[nt2][2] + obuf[(r0+8) * OP + col])   * inv1;
            float a3 = (o_acc[nt2][3] + obuf[(r0+8) * OP + col+1]) * inv1;
            *reinterpret_cast<float2*>(Og + (long)gr * DM + col)       = make_float2(a0, a1);
            *reinterpret_cast<float2*>(Og + (long)(gr + 8) * DM + col) = make_float2(a2, a3);
        }
    }
}

// ---------------------------------------------------------------------------
// NT GEMM via mma.sync bf16, 3-term split: C = A[M,K] @ B[N,K]^T
// MODE 0: plain fp32 store (C).
// MODE 1: bf16 hi/lo plane store (C=hi, C2=lo), same layout as MODE 0.
// MODE 3: transposed per-head bf16 hi/lo store -> vt[bh][d][s] (C=hi, C2=lo).
// BM=BN=128, BK=32. 256 threads.
// ---------------------------------------------------------------------------
template<int MODE>
__global__ void __launch_bounds__(256, 1) gemm_nt_mma(
    const float* __restrict__ A, const float* __restrict__ B,
    float* __restrict__ C, float* __restrict__ C2,
    int K, int lda, int ldb, int ldc)
{
    constexpr int BM = 128, BN = 128, BK = 32;
    constexpr int ROWB = 80;
    constexpr int A_PLANE = BM * ROWB;
    constexpr int B_PLANE = BN * ROWB;
    constexpr int STAGE = 2 * A_PLANE + 2 * B_PLANE;

    extern __shared__ char smem[];
    const uint32_t sb = smem_u32(smem);

    const int tid = threadIdx.x, lane = tid & 31, wid = tid >> 5;
    const int wm = wid & 1, wn = wid >> 1;
    const int brow = blockIdx.y * BM;
    const int bcol = blockIdx.x * BN;

    float acc[4][4][4];
#pragma unroll
    for (int i = 0; i < 4; i++)
#pragma unroll
        for (int j = 0; j < 4; j++)
#pragma unroll
            for (int r = 0; r < 4; r++) acc[i][j][r] = 0.0f;

    float4 va[4], vb[4];
    const int nc = K / BK;

    const int g = lane >> 3;
    const int lrow = (lane & 7) + ((g & 1) << 3);
    const int lc16 = (g >> 1) << 4;

    // prologue: chunk 0 -> buffer 0
    {
#pragma unroll
        for (int i = 0; i < 4; i++) {
            int f = tid + i * 256, r = f >> 3, fi = f & 7;
            va[i] = *reinterpret_cast<const float4*>(A + (long)(brow + r) * lda + fi * 4);
            vb[i] = *reinterpret_cast<const float4*>(B + (long)(bcol + r) * ldb + fi * 4);
        }
        char* st = smem;
#pragma unroll
        for (int i = 0; i < 4; i++) {
            int f = tid + i * 256, r = f >> 3, fi = f & 7;
            uint32_t h0, l0, h1, l1;
            split2(va[i].x, va[i].y, h0, l0); split2(va[i].z, va[i].w, h1, l1);
            *reinterpret_cast<uint2*>(st + r * ROWB + fi * 8)           = make_uint2(h0, h1);
            *reinterpret_cast<uint2*>(st + A_PLANE + r * ROWB + fi * 8) = make_uint2(l0, l1);
            split2(vb[i].x, vb[i].y, h0, l0); split2(vb[i].z, vb[i].w, h1, l1);
            *reinterpret_cast<uint2*>(st + 2 * A_PLANE + r * ROWB + fi * 8)           = make_uint2(h0, h1);
            *reinterpret_cast<uint2*>(st + 2 * A_PLANE + B_PLANE + r * ROWB + fi * 8) = make_uint2(l0, l1);
        }
    }

    for (int c = 0; c < nc; ++c) {
        __syncthreads();
        const int buf = c & 1;

        if (c + 1 < nc) {
            const int k0 = (c + 1) * BK;
#pragma unroll
            for (int i = 0; i < 4; i++) {
                int f = tid + i * 256, r = f >> 3, fi = f & 7;
                va[i] = *reinterpret_cast<const float4*>(A + (long)(brow + r) * lda + k0 + fi * 4);
                vb[i] = *reinterpret_cast<const float4*>(B + (long)(bcol + r) * ldb + k0 + fi * 4);
            }
        }

        {
            const uint32_t aHi = sb + buf * STAGE;
            const uint32_t aLo = aHi + A_PLANE;
            const uint32_t bHi = aHi + 2 * A_PLANE;
            const uint32_t bLo = bHi + B_PLANE;
#pragma unroll
            for (int kg = 0; kg < 2; kg++) {
                const int kb = kg * 32 + lc16;
                uint32_t a_h[4][4], a_l[4][4];
#pragma unroll
                for (int mt = 0; mt < 4; mt++) {
                    int r0 = wm * 64 + mt * 16 + lrow;
                    ldm4(aHi + r0 * ROWB + kb, a_h[mt]);
                    ldm4(aLo + r0 * ROWB + kb, a_l[mt]);
                }
                uint32_t b_h[4][2], b_l[4][2];
#pragma unroll
                for (int np = 0; np < 2; np++) {
                    int n0 = wn * 32 + np * 16 + lrow;
                    uint32_t t[4];
                    ldm4(bHi + n0 * ROWB + kb, t);
                    b_h[2*np][0] = t[0]; b_h[2*np+1][0] = t[1];
                    b_h[2*np][1] = t[2]; b_h[2*np+1][1] = t[3];
                    ldm4(bLo + n0 * ROWB + kb, t);
                    b_l[2*np][0] = t[0]; b_l[2*np+1][0] = t[1];
                    b_l[2*np][1] = t[2]; b_l[2*np+1][1] = t[3];
                }
#pragma unroll
                for (int mt = 0; mt < 4; mt++)
#pragma unroll
                    for (int nt = 0; nt < 4; nt++) {
                        mma16816(acc[mt][nt], a_h[mt], b_h[nt]);
                        mma16816(acc[mt][nt], a_h[mt], b_l[nt]);
                        mma16816(acc[mt][nt], a_l[mt], b_h[nt]);
                    }
            }
        }

        if (c + 1 < nc) {
            char* st = smem + (buf ^ 1) * STAGE;
#pragma unroll
            for (int i = 0; i < 4; i++) {
                int f = tid + i * 256, r = f >> 3, fi = f & 7;
                uint32_t h0, l0, h1, l1;
                split2(va[i].x, va[i].y, h0, l0); split2(va[i].z, va[i].w, h1, l1);
                *reinterpret_cast<uint2*>(st + r * ROWB + fi * 8)           = make_uint2(h0, h1);
                *reinterpret_cast<uint2*>(st + A_PLANE + r * ROWB + fi * 8) = make_uint2(l0, l1);
                split2(vb[i].x, vb[i].y, h0, l0); split2(vb[i].z, vb[i].w, h1, l1);
                *reinterpret_cast<uint2*>(st + 2 * A_PLANE + r * ROWB + fi * 8)           = make_uint2(h0, h1);
                *reinterpret_cast<uint2*>(st + 2 * A_PLANE + B_PLANE + r * ROWB + fi * 8) = make_uint2(l0, l1);
            }
        }
    }

    if (MODE == 0) {
#pragma unroll
        for (int mt = 0; mt < 4; mt++)
#pragma unroll
            for (int nt = 0; nt < 4; nt++) {
                long row = brow + wm * 64 + mt * 16 + (lane >> 2);
                long col = bcol + wn * 32 + nt * 8 + (lane & 3) * 2;
                *reinterpret_cast<float2*>(C + row * ldc + col) =
                    make_float2(acc[mt][nt][0], acc[mt][nt][1]);
                *reinterpret_cast<float2*>(C + (row + 8) * ldc + col) =
                    make_float2(acc[mt][nt][2], acc[mt][nt][3]);
            }
    } else if (MODE == 1) {
        __nv_bfloat16* hiP = reinterpret_cast<__nv_bfloat16*>(C);
        __nv_bfloat16* loP = reinterpret_cast<__nv_bfloat16*>(C2);
#pragma unroll
        for (int mt = 0; mt < 4; mt++)
#pragma unroll
            for (int nt = 0; nt < 4; nt++) {
                long row = brow + wm * 64 + mt * 16 + (lane >> 2);
                long col = bcol + wn * 32 + nt * 8 + (lane & 3) * 2;
                uint32_t h0, l0, h1, l1;
                split2(acc[mt][nt][0], acc[mt][nt][1], h0, l0);
                split2(acc[mt][nt][2], acc[mt][nt][3], h1, l1);
                *reinterpret_cast<uint32_t*>(hiP + row * ldc + col)       = h0;
                *reinterpret_cast<uint32_t*>(loP + row * ldc + col)       = l0;
                *reinterpret_cast<uint32_t*>(hiP + (row + 8) * ldc + col) = h1;
                *reinterpret_cast<uint32_t*>(loP + (row + 8) * ldc + col) = l1;
            }
    } else {
        // MODE 3: transpose via smem (fp32), then split + write bf16 planes
        constexpr int TP = 132;
        __syncthreads();
        float* tb = reinterpret_cast<float*>(smem);  // [128 d][132 s]
#pragma unroll
        for (int mt = 0; mt < 4; mt++)
#pragma unroll
            for (int nt = 0; nt < 4; nt++) {
                int s0 = wm * 64 + mt * 16 + (lane >> 2);
                int d0 = wn * 32 + nt * 8 + (lane & 3) * 2;
                tb[d0 * TP + s0]           = acc[mt][nt][0];
                tb[(d0 + 1) * TP + s0]     = acc[mt][nt][1];
                tb[d0 * TP + s0 + 8]       = acc[mt][nt][2];
                tb[(d0 + 1) * TP + s0 + 8] = acc[mt][nt][3];
            }
        __syncthreads();
        __nv_bfloat16* hiP = reinterpret_cast<__nv_bfloat16*>(C);
        __nv_bfloat16* loP = reinterpret_cast<__nv_bfloat16*>(C2);
        const int bb = brow >> 11;          // batch
        const int srow0 = brow & 2047;
        const int h0i = bcol >> 6;          // first of 2 heads in this col block
#pragma unroll
        for (int i = 0; i < 16; i++) {
            int f = tid + i * 256;
            int d = f >> 5, s = (f & 31) * 4;
            float4 v = *reinterpret_cast<float4*>(&tb[d * TP + s]);
            int hh = h0i + (d >> 6), dd = d & 63;
            long off = ((long)(bb * NH + hh) * HD + dd) * SEQ + srow0 + s;
            uint32_t h0, l0, h1, l1;
            split2(v.x, v.y, h0, l0); split2(v.z, v.w, h1, l1);
            *reinterpret_cast<uint2*>(hiP + off) = make_uint2(h0, h1);
            *reinterpret_cast<uint2*>(loP + off) = make_uint2(l0, l1);
        }
    }
}

// ---------------------------------------------------------------------------
// attn[row][:] *= pinv[row]  (one block per row, 256 thr x 2 float4)
// ---------------------------------------------------------------------------
__global__ void __launch_bounds__(256) normalize_attn(
    float* __restrict__ attn, const float* __restrict__ pinv)
{
    long row = blockIdx.x;
    float inv = pinv[row];
    float4* p = reinterpret_cast<float4*>(attn + row * 2048);
    int t = threadIdx.x;
    float4 a = p[t];
    a.x *= inv; a.y *= inv; a.z *= inv; a.w *= inv;
    p[t] = a;
    float4 c = p[t + 256];
    c.x *= inv; c.y *= inv; c.z *= inv; c.w *= inv;
    p[t + 256] = c;
}

// ---------------------------------------------------------------------------
extern "C" void kernel_launch(void* const* d_in, const int* in_sizes, int n_in,
                              void* d_out, int out_size)
{
    const float* x  = (const float*)d_in[0];
    const float* Wq = (const float*)d_in[1];
    const float* Wk = (const float*)d_in[2];
    const float* Wv = (const float*)d_in[3];
    const float* Wo = (const float*)d_in[4];
    float* out = (float*)d_out;

    float *q, *o, *pinv;
    __nv_bfloat16 *khi, *klo, *vthi, *vtlo;
    cudaGetSymbolAddress((void**)&q,    g_q);
    cudaGetSymbolAddress((void**)&khi,  g_khi);
    cudaGetSymbolAddress((void**)&klo,  g_klo);
    cudaGetSymbolAddress((void**)&vthi, g_vthi);
    cudaGetSymbolAddress((void**)&vtlo, g_vtlo);
    cudaGetSymbolAddress((void**)&o,    g_o);
    cudaGetSymbolAddress((void**)&pinv, g_pinv);

    const long OUT_ELEMS = (long)MTOT * DM;      // 4194304
    float* attn = out + OUT_ELEMS;               // verified layout

    constexpr int SMEMG = 2 * (2 * 128 * 80 + 2 * 128 * 80);  // 81920
    constexpr int SMEMF = 110592 + 2 * 2 * 17408;             // 180224
    cudaFuncSetAttribute(gemm_nt_mma<0>, cudaFuncAttributeMaxDynamicSharedMemorySize, SMEMG);
    cudaFuncSetAttribute(gemm_nt_mma<1>, cudaFuncAttributeMaxDynamicSharedMemorySize, SMEMG);
    cudaFuncSetAttribute(gemm_nt_mma<3>, cudaFuncAttributeMaxDynamicSharedMemorySize, SMEMG);
    cudaFuncSetAttribute(attn_fused,     cudaFuncAttributeMaxDynamicSharedMemorySize, SMEMF);

    const float scale = 0.125f;  // 1/sqrt(64)
    dim3 thr(256);
    dim3 gproj(DM / 128, MTOT / 128, 1);

    // 0) V projection -> transposed bf16 hi/lo planes
    gemm_nt_mma<3><<<gproj, thr, SMEMG>>>(x, Wv, (float*)vthi, (float*)vtlo, DM, DM, DM, DM);
    // 1) K projection -> bf16 hi/lo planes
    gemm_nt_mma<1><<<gproj, thr, SMEMG>>>(x, Wk, (float*)khi, (float*)klo, DM, DM, DM, DM);
    // 2) Q projection -> fp32
    gemm_nt_mma<0><<<gproj, thr, SMEMG>>>(x, Wq, q, nullptr, DM, DM, DM, DM);

    // 3) fused: expP (unnormalized) + pinv + O (normalized)  [profiled slot]
    dim3 gf(1, SEQ / 128, NB * NH);
    attn_fused<<<gf, dim3(512), SMEMF>>>(q, khi, klo, vthi, vtlo, attn, o, pinv, scale);

    // 4) normalize attn in-place
    normalize_attn<<<NB * NH * SEQ, 256>>>(attn, pinv);

    // 5) out = O @ Wo^T
    gemm_nt_mma<0><<<gproj, thr, SMEMG>>>(o, Wo, out, nullptr, DM, DM, DM, DM);
}